// round 6
// baseline (speedup 1.0000x reference)
#include <cuda_runtime.h>
#include <cuda_bf16.h>
#include <cstdint>
#include <cstddef>

// ===========================================================================
// Who2com forward — split-bf16 mma.sync implicit-GEMM convs.
// R6: K=32 chunks (80B pitch -> conflict-free ldmatrix), multi-stage cp.async
// with 1 sync/chunk, MTILE=64 small-conv variant with 2 CTAs/SM.
// ===========================================================================

__device__ __forceinline__ uint32_t smem_to_u32(const void* p) {
    uint32_t a;
    asm("{ .reg .u64 t; cvta.to.shared.u64 t, %1; cvt.u32.u64 %0, t; }"
        : "=r"(a) : "l"(p));
    return a;
}
__device__ __forceinline__ void ldsm_x4(uint32_t (&r)[4], uint32_t addr) {
    asm volatile("ldmatrix.sync.aligned.m8n8.x4.shared.b16 {%0,%1,%2,%3}, [%4];"
                 : "=r"(r[0]), "=r"(r[1]), "=r"(r[2]), "=r"(r[3]) : "r"(addr));
}
__device__ __forceinline__ void mma_bf16(float (&d)[4], const uint32_t (&a)[4],
                                         uint32_t b0, uint32_t b1) {
    asm volatile(
        "mma.sync.aligned.m16n8k16.row.col.f32.bf16.bf16.f32 "
        "{%0,%1,%2,%3}, {%4,%5,%6,%7}, {%8,%9}, {%0,%1,%2,%3};"
        : "+f"(d[0]), "+f"(d[1]), "+f"(d[2]), "+f"(d[3])
        : "r"(a[0]), "r"(a[1]), "r"(a[2]), "r"(a[3]), "r"(b0), "r"(b1));
}
__device__ __forceinline__ uint32_t pack_bf2(__nv_bfloat16 a, __nv_bfloat16 b) {
    __nv_bfloat162 t = __halves2bfloat162(a, b);
    return *reinterpret_cast<uint32_t*>(&t);
}
__device__ __forceinline__ void cp16(uint32_t dst, const void* src, bool v) {
    asm volatile("cp.async.cg.shared.global [%0], [%1], 16, %2;"
                 :: "r"(dst), "l"(src), "r"(v ? 16u : 0u) : "memory");
}
#define CP_COMMIT() asm volatile("cp.async.commit_group;" ::: "memory")

// ---------------------------------------------------------------------------
// Scratch
// ---------------------------------------------------------------------------
__device__ __align__(16) __nv_bfloat16 g_a0h[(size_t)160 * 256 * 256];
__device__ __align__(16) __nv_bfloat16 g_a0l[(size_t)160 * 256 * 256];
__device__ __align__(16) __nv_bfloat16 g_b1h[(size_t)160 * 256 * 512];
__device__ __align__(16) __nv_bfloat16 g_b1l[(size_t)160 * 256 * 512];
__device__ __align__(16) __nv_bfloat16 g_b2h[(size_t)160 * 256 * 256];
__device__ __align__(16) __nv_bfloat16 g_b2l[(size_t)160 * 256 * 256];
__device__ __align__(16) __nv_bfloat16 g_b3h[(size_t)160 * 64 * 256];
__device__ __align__(16) __nv_bfloat16 g_b3l[(size_t)160 * 64 * 256];
__device__ __align__(16) __nv_bfloat16 g_b4h[(size_t)160 * 64 * 256];
__device__ __align__(16) __nv_bfloat16 g_b4l[(size_t)160 * 64 * 256];
__device__ float g_feat[(size_t)160 * 4096];
__device__ float g_m1[160 * 256];
__device__ float g_m2[160 * 128];
__device__ float g_keys[160 * 1024];
__device__ float g_qrys[160 * 32];
__device__ float g_qq[160 * 1024];
__device__ float g_wf[32 * 5];
__device__ __align__(16) __nv_bfloat16 g_w1h[512 * 2304], g_w1l[512 * 2304];
__device__ __align__(16) __nv_bfloat16 g_w2h[256 * 4608], g_w2l[256 * 4608];
__device__ __align__(16) __nv_bfloat16 g_w3h[256 * 2304], g_w3l[256 * 2304];
__device__ __align__(16) __nv_bfloat16 g_w4h[256 * 2304], g_w4l[256 * 2304];
__device__ __align__(16) __nv_bfloat16 g_w5h[256 * 2304], g_w5l[256 * 2304];

// ---------------------------------------------------------------------------
// Weight prep: src[co][ci][kh][kw] -> hi/lo bf16 at [co][(kh*3+kw)*CIN + ci]
// ---------------------------------------------------------------------------
__global__ void wprep_kernel(const float* __restrict__ w, __nv_bfloat16* __restrict__ hi,
                             __nv_bfloat16* __restrict__ lo, int COUT, int CIN)
{
    int total = COUT * CIN * 9;
    for (int idx = blockIdx.x * blockDim.x + threadIdx.x; idx < total;
         idx += gridDim.x * blockDim.x) {
        int co = idx / (CIN * 9);
        int rem = idx - co * (CIN * 9);
        int ci = rem / 9, tap = rem - ci * 9;
        float v = w[idx];
        __nv_bfloat16 h = __float2bfloat16(v);
        __nv_bfloat16 l = __float2bfloat16(v - __bfloat162float(h));
        size_t d = (size_t)co * (CIN * 9) + tap * CIN + ci;
        hi[d] = h; lo[d] = l;
    }
}

// bevs NCHW fp32 -> NHWC hi/lo bf16.
__global__ void actsplit_kernel(const float* __restrict__ in,
                                __nv_bfloat16* __restrict__ oh,
                                __nv_bfloat16* __restrict__ ol)
{
    __shared__ float s[32][257];
    int n = blockIdx.x, c0 = blockIdx.y * 32;
    int tid = threadIdx.x;
#pragma unroll
    for (int it = 0; it < 32; it++)
        s[it][tid] = in[((size_t)n * 256 + c0 + it) * 256 + tid];
    __syncthreads();
    int ci = tid & 31, p0 = tid >> 5;
#pragma unroll
    for (int pp = 0; pp < 32; pp++) {
        int pix = p0 + pp * 8;
        float v = s[ci][pix];
        __nv_bfloat16 h = __float2bfloat16(v);
        __nv_bfloat16 l = __float2bfloat16(v - __bfloat162float(h));
        size_t o = ((size_t)n * 256 + pix) * 256 + c0 + ci;
        oh[o] = h; ol[o] = l;
    }
}

// ---------------------------------------------------------------------------
// Implicit-GEMM conv3x3 (pad=1) + affine + ReLU, split-bf16 mma.sync.
// K-chunks of 32 (80B smem pitch -> conflict-free ldmatrix), STAGES-deep
// cp.async pipeline, 1 __syncthreads per chunk.
// MTILE=128: 4 m-warps x 2 n-warps.  MTILE=64: 2 m-warps x 4 n-warps.
// ---------------------------------------------------------------------------
static constexpr int SPB = 80;  // smem row pitch bytes (32 bf16 + 16B pad)

template <int CIN, int COUT, int HIN, int WIN, int STRIDE, int OUTMODE,
          int MTILE, int STAGES, int MINCTA>
__global__ void __launch_bounds__(256, MINCTA)
convMMA_kernel(const __nv_bfloat16* __restrict__ aH, const __nv_bfloat16* __restrict__ aL,
               const __nv_bfloat16* __restrict__ wH, const __nv_bfloat16* __restrict__ wL,
               const float* __restrict__ scale, const float* __restrict__ shift,
               __nv_bfloat16* __restrict__ oH, __nv_bfloat16* __restrict__ oL,
               float* __restrict__ oF)
{
    constexpr int HO   = (HIN - 1) / STRIDE + 1;
    constexpr int WO   = (WIN - 1) / STRIDE + 1;
    constexpr int MPIX = HO * WO;
    constexpr int NIMG = (MPIX >= MTILE) ? 1 : (MTILE / MPIX);
    constexpr int NT   = COUT / 128;
    constexpr int KTOT = 9 * CIN;
    constexpr int CPT  = CIN / 32;       // K-chunks per tap
    constexpr int NCH  = 9 * CPT;
    constexpr int MW   = MTILE / 32;     // m-warps
    constexpr int NW   = 8 / MW;         // n-warps
    constexpr int NCPW = 128 / NW;       // cout per warp
    constexpr int NT2  = NCPW / 16;
    constexpr int STB  = (MTILE + 128) * 2 * SPB;   // stage bytes
    constexpr int A_LO = MTILE * SPB;
    constexpr int B_HI = MTILE * 2 * SPB;
    constexpr int B_LO = B_HI + 128 * SPB;
    constexpr int RT8  = (MTILE + 128) * 8;         // cp16 transfers per stage

    extern __shared__ char smem[];
    const uint32_t sb = smem_to_u32(smem);

    const int tid = threadIdx.x, wid = tid >> 5, lane = tid & 31;
    const int mt  = blockIdx.x / NT;
    const int co0 = (blockIdx.x % NT) * 128;
    const int n0  = blockIdx.y * NIMG;
    const int wm  = wid % MW;
    const int wn  = wid / MW;

    auto issue = [&](int c) {
        const uint32_t st = sb + (uint32_t)(c % STAGES) * STB;
        const int tap = c / CPT;
        const int ci0 = (c - tap * CPT) * 32;
        const int dy = tap / 3 - 1, dx = tap % 3 - 1;
#pragma unroll
        for (int i = tid; i < RT8; i += 256) {
            const int row  = i >> 3;
            const int seg  = i & 3;
            const int half = (i >> 2) & 1;
            if (row < MTILE) {
                int g = mt * MTILE + row;
                int img = g / MPIX, pix = g % MPIX;
                int oh = pix / WO, ow = pix - oh * WO;
                int ih = oh * STRIDE + dy, iw = ow * STRIDE + dx;
                bool v = ((unsigned)ih < (unsigned)HIN) && ((unsigned)iw < (unsigned)WIN);
                int ihs = v ? ih : 0, iws = v ? iw : 0;
                size_t aoff = (((size_t)(n0 + img) * HIN + ihs) * WIN + iws) * CIN
                              + ci0 + seg * 8;
                uint32_t ad = st + (uint32_t)half * A_LO + (uint32_t)row * SPB + seg * 16;
                cp16(ad, (half ? aL : aH) + aoff, v);
            } else {
                int r2 = row - MTILE;
                size_t woff = (size_t)(co0 + r2) * KTOT + (size_t)c * 32 + seg * 8;
                uint32_t bd = st + B_HI + (uint32_t)half * (128 * SPB)
                              + (uint32_t)r2 * SPB + seg * 16;
                cp16(bd, (half ? wL : wH) + woff, true);
            }
        }
        CP_COMMIT();
    };

    float acc[2][NT2 * 2][4];
#pragma unroll
    for (int a = 0; a < 2; a++)
#pragma unroll
        for (int b = 0; b < NT2 * 2; b++)
#pragma unroll
            for (int c = 0; c < 4; c++) acc[a][b][c] = 0.f;

    // prologue: STAGES-1 chunks in flight
#pragma unroll
    for (int p = 0; p < STAGES - 1; p++) issue(p);

    for (int c = 0; c < NCH; c++) {
        if (STAGES == 4)
            asm volatile("cp.async.wait_group 2;" ::: "memory");
        else
            asm volatile("cp.async.wait_group 1;" ::: "memory");
        __syncthreads();
        if (c + STAGES - 1 < NCH) issue(c + STAGES - 1);
        else CP_COMMIT();

        const uint32_t st  = sb + (uint32_t)(c % STAGES) * STB;
        const uint32_t sAh = st, sAl = st + A_LO, sBh = st + B_HI, sBl = st + B_LO;
#pragma unroll
        for (int ks = 0; ks < 2; ks++) {
            const uint32_t acol = (uint32_t)ks * 32u + ((lane >> 4) << 4);
            uint32_t ah[2][4], al2[2][4];
#pragma unroll
            for (int m2 = 0; m2 < 2; m2++) {
                uint32_t arow = (uint32_t)(wm * 32 + m2 * 16 + (lane & 15));
                ldsm_x4(ah[m2],  sAh + arow * SPB + acol);
                ldsm_x4(al2[m2], sAl + arow * SPB + acol);
            }
#pragma unroll
            for (int nt2 = 0; nt2 < NT2; nt2++) {
                uint32_t brow = (uint32_t)(wn * NCPW + nt2 * 16 +
                                           ((lane >> 4) << 3) + (lane & 7));
                uint32_t bcol = (uint32_t)ks * 32u + (((lane >> 3) & 1) << 4);
                uint32_t bh[4], bl4[4];
                ldsm_x4(bh, sBh + brow * SPB + bcol);
#pragma unroll
                for (int m2 = 0; m2 < 2; m2++) {
                    mma_bf16(acc[m2][nt2 * 2],     ah[m2], bh[0], bh[1]);
                    mma_bf16(acc[m2][nt2 * 2 + 1], ah[m2], bh[2], bh[3]);
                }
                ldsm_x4(bl4, sBl + brow * SPB + bcol);
#pragma unroll
                for (int m2 = 0; m2 < 2; m2++) {
                    mma_bf16(acc[m2][nt2 * 2],     ah[m2], bl4[0], bl4[1]);
                    mma_bf16(acc[m2][nt2 * 2 + 1], ah[m2], bl4[2], bl4[3]);
                    mma_bf16(acc[m2][nt2 * 2],     al2[m2], bh[0], bh[1]);
                    mma_bf16(acc[m2][nt2 * 2 + 1], al2[m2], bh[2], bh[3]);
                }
            }
        }
    }

    if (OUTMODE == 0) {
        // ---- NHWC hi/lo epilogue: direct from fragments ----
#pragma unroll
        for (int m2 = 0; m2 < 2; m2++) {
            int mA = wm * 32 + m2 * 16 + (lane >> 2);
            int gA = mt * MTILE + mA;
            int gB = gA + 8;
            size_t rowA = ((size_t)(n0 + gA / MPIX) * MPIX + gA % MPIX) * COUT;
            size_t rowB = ((size_t)(n0 + gB / MPIX) * MPIX + gB % MPIX) * COUT;
#pragma unroll
            for (int j = 0; j < NT2 * 2; j++) {
                int co = co0 + wn * NCPW + j * 8 + (lane & 3) * 2;
                float s0 = __ldg(scale + co), s1 = __ldg(scale + co + 1);
                float t0 = __ldg(shift + co), t1 = __ldg(shift + co + 1);
                float v0 = fmaxf(fmaf(acc[m2][j][0], s0, t0), 0.f);
                float v1 = fmaxf(fmaf(acc[m2][j][1], s1, t1), 0.f);
                float v2 = fmaxf(fmaf(acc[m2][j][2], s0, t0), 0.f);
                float v3 = fmaxf(fmaf(acc[m2][j][3], s1, t1), 0.f);
                __nv_bfloat16 h0 = __float2bfloat16(v0), h1 = __float2bfloat16(v1);
                __nv_bfloat16 h2 = __float2bfloat16(v2), h3 = __float2bfloat16(v3);
                __nv_bfloat16 l0 = __float2bfloat16(v0 - __bfloat162float(h0));
                __nv_bfloat16 l1 = __float2bfloat16(v1 - __bfloat162float(h1));
                __nv_bfloat16 l2 = __float2bfloat16(v2 - __bfloat162float(h2));
                __nv_bfloat16 l3 = __float2bfloat16(v3 - __bfloat162float(h3));
                *reinterpret_cast<uint32_t*>(oH + rowA + co) = pack_bf2(h0, h1);
                *reinterpret_cast<uint32_t*>(oL + rowA + co) = pack_bf2(l0, l1);
                *reinterpret_cast<uint32_t*>(oH + rowB + co) = pack_bf2(h2, h3);
                *reinterpret_cast<uint32_t*>(oL + rowB + co) = pack_bf2(l2, l3);
            }
        }
    } else {
        // ---- CHW fp32 epilogue (conv5 -> feats): transpose via smem ----
        constexpr int OPITCH = MTILE + 4;
        float* sOut = reinterpret_cast<float*>(smem);
        __syncthreads();
#pragma unroll
        for (int m2 = 0; m2 < 2; m2++) {
#pragma unroll
            for (int j = 0; j < NT2 * 2; j++) {
                int m = wm * 32 + m2 * 16 + (lane >> 2);
                int nn = wn * NCPW + j * 8 + (lane & 3) * 2;
                sOut[(size_t)nn * OPITCH + m]           = acc[m2][j][0];
                sOut[(size_t)(nn + 1) * OPITCH + m]     = acc[m2][j][1];
                sOut[(size_t)nn * OPITCH + m + 8]       = acc[m2][j][2];
                sOut[(size_t)(nn + 1) * OPITCH + m + 8] = acc[m2][j][3];
            }
        }
        __syncthreads();
        int row = tid >> 1, half = tid & 1;
        int co = co0 + row;
        float s = __ldg(scale + co), t = __ldg(shift + co);
#pragma unroll
        for (int q = 0; q < MTILE / 8; q++) {
            int m = half * (MTILE / 2) + q * 4;
            float4 v = *reinterpret_cast<float4*>(&sOut[(size_t)row * OPITCH + m]);
            v.x = fmaxf(fmaf(v.x, s, t), 0.f);
            v.y = fmaxf(fmaf(v.y, s, t), 0.f);
            v.z = fmaxf(fmaf(v.z, s, t), 0.f);
            v.w = fmaxf(fmaf(v.w, s, t), 0.f);
            int g = mt * MTILE + m;
            int img = g / MPIX, pix = g % MPIX;
            *reinterpret_cast<float4*>(
                &oF[((size_t)(n0 + img) * COUT + co) * MPIX + pix]) = v;
        }
    }
}

// ---------------------------------------------------------------------------
// Warp-tile GEMV: each warp computes a 4m x 8n tile of Y = X.W^T + b.
// ---------------------------------------------------------------------------
__global__ void warptile_kernel(const float* __restrict__ X, const float* __restrict__ W,
                                const float* __restrict__ bias, float* __restrict__ Y,
                                int M, int N, int K, int doRelu)
{
    int gw   = (blockIdx.x * blockDim.x + threadIdx.x) >> 5;
    int lane = threadIdx.x & 31;
    int nW = N >> 3;
    int mtile = gw / nW, ntile = gw - mtile * nW;
    if (mtile * 4 >= M) return;
    const float* x0 = X + (size_t)(mtile * 4) * K;
    const float* w0 = W + (size_t)(ntile * 8) * K;
    float acc[4][8];
#pragma unroll
    for (int i = 0; i < 4; i++)
#pragma unroll
        for (int j = 0; j < 8; j++) acc[i][j] = 0.f;
    for (int k = lane; k < K; k += 32) {
        float xv[4], wv[8];
#pragma unroll
        for (int i = 0; i < 4; i++) xv[i] = x0[(size_t)i * K + k];
#pragma unroll
        for (int j = 0; j < 8; j++) wv[j] = w0[(size_t)j * K + k];
#pragma unroll
        for (int i = 0; i < 4; i++)
#pragma unroll
            for (int j = 0; j < 8; j++) acc[i][j] = fmaf(xv[i], wv[j], acc[i][j]);
    }
#pragma unroll
    for (int o = 16; o; o >>= 1)
#pragma unroll
        for (int i = 0; i < 4; i++)
#pragma unroll
            for (int j = 0; j < 8; j++)
                acc[i][j] += __shfl_xor_sync(0xffffffffu, acc[i][j], o);
    int i = lane >> 3, j = lane & 7;
    float v = acc[i][j] + bias[ntile * 8 + j];
    if (doRelu) v = fmaxf(v, 0.f);
    Y[(size_t)(mtile * 4 + i) * N + ntile * 8 + j] = v;
}

// ---------------------------------------------------------------------------
// Attention + softmax -> fuse weights; final fuse.
// ---------------------------------------------------------------------------
__global__ void attn_kernel(const float* __restrict__ keys, const float* __restrict__ qq,
                            float* __restrict__ wf)
{
    int b = blockIdx.x;
    __shared__ float sA[5][5];
    int warp = threadIdx.x >> 5, lane = threadIdx.x & 31;
    for (int e = warp; e < 25; e += 8) {
        int i = e / 5, j = e - i * 5;
        const float4* kr = (const float4*)(keys + (size_t)(i * 32 + b) * 1024);
        const float4* qr = (const float4*)(qq + (size_t)(j * 32 + b) * 1024);
        float acc = 0.f;
        for (int k = lane; k < 256; k += 32) {
            float4 a = kr[k], c = qr[k];
            acc += a.x * c.x + a.y * c.y + a.z * c.z + a.w * c.w;
        }
#pragma unroll
        for (int o = 16; o; o >>= 1) acc += __shfl_xor_sync(0xffffffffu, acc, o);
        if (lane == 0) sA[i][j] = acc;
    }
    __syncthreads();
    if (threadIdx.x == 0) {
        float w[5] = {0.f, 0.f, 0.f, 0.f, 0.f};
        for (int j = 0; j < 5; j++) {
            float dd[4], mx = -1e30f;
            for (int r = 0; r < 4; r++) {
                dd[r] = (j > r) ? sA[r][j] : sA[r + 1][j];
                mx = fmaxf(mx, dd[r]);
            }
            float s = 0.f;
            for (int r = 0; r < 4; r++) { dd[r] = expf(dd[r] - mx); s += dd[r]; }
            float inv = 1.f / s;
            for (int r = 0; r < 4; r++) {
                int i = (j > r) ? r : r + 1;
                w[i] += dd[r] * inv;
            }
        }
        for (int i = 0; i < 5; i++) wf[b * 5 + i] = w[i] * 0.2f;
    }
}

__global__ void fuse_kernel(const float* __restrict__ bevs, const float* __restrict__ wf,
                            float* __restrict__ out)
{
    const int CHW = 256 * 16 * 16;
    int idx = blockIdx.x * blockDim.x + threadIdx.x;
    if (idx >= 32 * CHW) return;
    int b   = idx / CHW;
    int chw = idx - b * CHW;
    const float* base = bevs + ((size_t)b * 5) * CHW + chw;
    float acc = 0.f;
#pragma unroll
    for (int k = 0; k < 5; k++) acc += wf[b * 5 + k] * base[(size_t)k * CHW];
    out[idx] = acc;
}

// ---------------------------------------------------------------------------
extern "C" void kernel_launch(void* const* d_in, const int* in_sizes, int n_in,
                              void* d_out, int out_size)
{
    (void)in_sizes; (void)n_in; (void)out_size;
    const float* bevs = (const float*)d_in[0];
    const float *cw[5], *cs[5], *ct[5];
    for (int i = 0; i < 5; i++) {
        cw[i] = (const float*)d_in[1 + 3 * i];
        cs[i] = (const float*)d_in[2 + 3 * i];
        ct[i] = (const float*)d_in[3 + 3 * i];
    }
    const float* kw1 = (const float*)d_in[16]; const float* kb1 = (const float*)d_in[17];
    const float* kw2 = (const float*)d_in[18]; const float* kb2 = (const float*)d_in[19];
    const float* kw3 = (const float*)d_in[20]; const float* kb3 = (const float*)d_in[21];
    const float* qw1 = (const float*)d_in[22]; const float* qb1 = (const float*)d_in[23];
    const float* qw2 = (const float*)d_in[24]; const float* qb2 = (const float*)d_in[25];
    const float* qw3 = (const float*)d_in[26]; const float* qb3 = (const float*)d_in[27];
    const float* aw  = (const float*)d_in[28]; const float* ab  = (const float*)d_in[29];
    float* out = (float*)d_out;

    __nv_bfloat16 *a0h, *a0l, *b1h, *b1l, *b2h, *b2l, *b3h, *b3l, *b4h, *b4l;
    cudaGetSymbolAddress((void**)&a0h, g_a0h); cudaGetSymbolAddress((void**)&a0l, g_a0l);
    cudaGetSymbolAddress((void**)&b1h, g_b1h); cudaGetSymbolAddress((void**)&b1l, g_b1l);
    cudaGetSymbolAddress((void**)&b2h, g_b2h); cudaGetSymbolAddress((void**)&b2l, g_b2l);
    cudaGetSymbolAddress((void**)&b3h, g_b3h); cudaGetSymbolAddress((void**)&b3l, g_b3l);
    cudaGetSymbolAddress((void**)&b4h, g_b4h); cudaGetSymbolAddress((void**)&b4l, g_b4l);
    float *feat, *m1, *m2, *keys, *qrys, *qq, *wf;
    cudaGetSymbolAddress((void**)&feat, g_feat);
    cudaGetSymbolAddress((void**)&m1, g_m1);
    cudaGetSymbolAddress((void**)&m2, g_m2);
    cudaGetSymbolAddress((void**)&keys, g_keys);
    cudaGetSymbolAddress((void**)&qrys, g_qrys);
    cudaGetSymbolAddress((void**)&qq, g_qq);
    cudaGetSymbolAddress((void**)&wf, g_wf);
    __nv_bfloat16 *w1h, *w1l, *w2h, *w2l, *w3h, *w3l, *w4h, *w4l, *w5h, *w5l;
    cudaGetSymbolAddress((void**)&w1h, g_w1h); cudaGetSymbolAddress((void**)&w1l, g_w1l);
    cudaGetSymbolAddress((void**)&w2h, g_w2h); cudaGetSymbolAddress((void**)&w2l, g_w2l);
    cudaGetSymbolAddress((void**)&w3h, g_w3h); cudaGetSymbolAddress((void**)&w3l, g_w3l);
    cudaGetSymbolAddress((void**)&w4h, g_w4h); cudaGetSymbolAddress((void**)&w4l, g_w4l);
    cudaGetSymbolAddress((void**)&w5h, g_w5h); cudaGetSymbolAddress((void**)&w5l, g_w5l);

    // stage sizes: MTILE128 -> 40960B * 4 stages; MTILE64 -> 30720B * 3 stages
    constexpr int SMEM_L12 = 4 * 40960;   // 163840
    constexpr int SMEM_S   = 3 * 30720;   // 92160

    cudaFuncSetAttribute(convMMA_kernel<256, 512, 16, 16, 1, 0, 128, 4, 1>,
                         cudaFuncAttributeMaxDynamicSharedMemorySize, SMEM_L12);
    cudaFuncSetAttribute(convMMA_kernel<512, 256, 16, 16, 1, 0, 128, 4, 1>,
                         cudaFuncAttributeMaxDynamicSharedMemorySize, SMEM_L12);
    cudaFuncSetAttribute(convMMA_kernel<256, 256, 16, 16, 2, 0, 64, 3, 2>,
                         cudaFuncAttributeMaxDynamicSharedMemorySize, SMEM_S);
    cudaFuncSetAttribute(convMMA_kernel<256, 256, 8, 8, 1, 0, 64, 3, 2>,
                         cudaFuncAttributeMaxDynamicSharedMemorySize, SMEM_S);
    cudaFuncSetAttribute(convMMA_kernel<256, 256, 8, 8, 2, 1, 64, 3, 2>,
                         cudaFuncAttributeMaxDynamicSharedMemorySize, SMEM_S);

    // prep: weight splits + bevs NCHW->NHWC split
    wprep_kernel<<<512, 256>>>(cw[0], w1h, w1l, 512, 256);
    wprep_kernel<<<512, 256>>>(cw[1], w2h, w2l, 256, 512);
    wprep_kernel<<<512, 256>>>(cw[2], w3h, w3l, 256, 256);
    wprep_kernel<<<512, 256>>>(cw[3], w4h, w4l, 256, 256);
    wprep_kernel<<<512, 256>>>(cw[4], w5h, w5l, 256, 256);
    actsplit_kernel<<<dim3(160, 8), 256>>>(bevs, a0h, a0l);

    // conv stack
    convMMA_kernel<256, 512, 16, 16, 1, 0, 128, 4, 1><<<dim3(8, 160), 256, SMEM_L12>>>(
        a0h, a0l, w1h, w1l, cs[0], ct[0], b1h, b1l, nullptr);
    convMMA_kernel<512, 256, 16, 16, 1, 0, 128, 4, 1><<<dim3(4, 160), 256, SMEM_L12>>>(
        b1h, b1l, w2h, w2l, cs[1], ct[1], b2h, b2l, nullptr);
    convMMA_kernel<256, 256, 16, 16, 2, 0, 64, 3, 2><<<dim3(2, 160), 256, SMEM_S>>>(
        b2h, b2l, w3h, w3l, cs[2], ct[2], b3h, b3l, nullptr);
    convMMA_kernel<256, 256, 8, 8, 1, 0, 64, 3, 2><<<dim3(2, 160), 256, SMEM_S>>>(
        b3h, b3l, w4h, w4l, cs[3], ct[3], b4h, b4l, nullptr);
    convMMA_kernel<256, 256, 8, 8, 2, 1, 64, 3, 2><<<dim3(2, 40), 256, SMEM_S>>>(
        b4h, b4l, w5h, w5l, cs[4], ct[4], nullptr, nullptr, feat);

    // MLPs + projection
    auto wt = [&](const float* X, const float* W, const float* B, float* Y,
                  int M, int N, int K, int relu) {
        int warps = (M / 4) * (N / 8);
        warptile_kernel<<<(warps + 7) / 8, 256>>>(X, W, B, Y, M, N, K, relu);
    };
    wt(feat, kw1, kb1, m1,   160,  256, 4096, 1);
    wt(m1,   kw2, kb2, m2,   160,  128,  256, 1);
    wt(m2,   kw3, kb3, keys, 160, 1024,  128, 0);
    wt(feat, qw1, qb1, m1,   160,  256, 4096, 1);
    wt(m1,   qw2, qb2, m2,   160,  128,  256, 1);
    wt(m2,   qw3, qb3, qrys, 160,   32,  128, 0);
    wt(qrys, aw,  ab,  qq,   160, 1024,   32, 0);

    attn_kernel<<<32, 256>>>(keys, qq, wf);
    fuse_kernel<<<(32 * 256 * 16 * 16 + 255) / 256, 256>>>(bevs, wf, out);
}

// round 7
// speedup vs baseline: 1.0946x; 1.0946x over previous
#include <cuda_runtime.h>
#include <cuda_bf16.h>
#include <cstdint>
#include <cstddef>

// ===========================================================================
// Who2com forward — split-bf16 mma.sync implicit-GEMM convs.
// R7: R5 core (K=64 chunks, 144B pitch) + circular stages w/ 1 sync per
// chunk; small convs MTILE=64 @ 2 CTAs/SM for full-wave occupancy.
// ===========================================================================

__device__ __forceinline__ uint32_t smem_to_u32(const void* p) {
    uint32_t a;
    asm("{ .reg .u64 t; cvta.to.shared.u64 t, %1; cvt.u32.u64 %0, t; }"
        : "=r"(a) : "l"(p));
    return a;
}
__device__ __forceinline__ void ldsm_x4(uint32_t (&r)[4], uint32_t addr) {
    asm volatile("ldmatrix.sync.aligned.m8n8.x4.shared.b16 {%0,%1,%2,%3}, [%4];"
                 : "=r"(r[0]), "=r"(r[1]), "=r"(r[2]), "=r"(r[3]) : "r"(addr));
}
__device__ __forceinline__ void mma_bf16(float (&d)[4], const uint32_t (&a)[4],
                                         uint32_t b0, uint32_t b1) {
    asm volatile(
        "mma.sync.aligned.m16n8k16.row.col.f32.bf16.bf16.f32 "
        "{%0,%1,%2,%3}, {%4,%5,%6,%7}, {%8,%9}, {%0,%1,%2,%3};"
        : "+f"(d[0]), "+f"(d[1]), "+f"(d[2]), "+f"(d[3])
        : "r"(a[0]), "r"(a[1]), "r"(a[2]), "r"(a[3]), "r"(b0), "r"(b1));
}
__device__ __forceinline__ uint32_t pack_bf2(__nv_bfloat16 a, __nv_bfloat16 b) {
    __nv_bfloat162 t = __halves2bfloat162(a, b);
    return *reinterpret_cast<uint32_t*>(&t);
}
__device__ __forceinline__ void cp16(uint32_t dst, const void* src, bool v) {
    asm volatile("cp.async.cg.shared.global [%0], [%1], 16, %2;"
                 :: "r"(dst), "l"(src), "r"(v ? 16u : 0u) : "memory");
}
#define CP_COMMIT() asm volatile("cp.async.commit_group;" ::: "memory")

// ---------------------------------------------------------------------------
// Scratch
// ---------------------------------------------------------------------------
__device__ __align__(16) __nv_bfloat16 g_a0h[(size_t)160 * 256 * 256];
__device__ __align__(16) __nv_bfloat16 g_a0l[(size_t)160 * 256 * 256];
__device__ __align__(16) __nv_bfloat16 g_b1h[(size_t)160 * 256 * 512];
__device__ __align__(16) __nv_bfloat16 g_b1l[(size_t)160 * 256 * 512];
__device__ __align__(16) __nv_bfloat16 g_b2h[(size_t)160 * 256 * 256];
__device__ __align__(16) __nv_bfloat16 g_b2l[(size_t)160 * 256 * 256];
__device__ __align__(16) __nv_bfloat16 g_b3h[(size_t)160 * 64 * 256];
__device__ __align__(16) __nv_bfloat16 g_b3l[(size_t)160 * 64 * 256];
__device__ __align__(16) __nv_bfloat16 g_b4h[(size_t)160 * 64 * 256];
__device__ __align__(16) __nv_bfloat16 g_b4l[(size_t)160 * 64 * 256];
__device__ float g_feat[(size_t)160 * 4096];
__device__ float g_m1[160 * 256];
__device__ float g_m2[160 * 128];
__device__ float g_keys[160 * 1024];
__device__ float g_qrys[160 * 32];
__device__ float g_qq[160 * 1024];
__device__ float g_wf[32 * 5];
__device__ __align__(16) __nv_bfloat16 g_w1h[512 * 2304], g_w1l[512 * 2304];
__device__ __align__(16) __nv_bfloat16 g_w2h[256 * 4608], g_w2l[256 * 4608];
__device__ __align__(16) __nv_bfloat16 g_w3h[256 * 2304], g_w3l[256 * 2304];
__device__ __align__(16) __nv_bfloat16 g_w4h[256 * 2304], g_w4l[256 * 2304];
__device__ __align__(16) __nv_bfloat16 g_w5h[256 * 2304], g_w5l[256 * 2304];

// ---------------------------------------------------------------------------
// Weight prep: src[co][ci][kh][kw] -> hi/lo bf16 at [co][(kh*3+kw)*CIN + ci]
// ---------------------------------------------------------------------------
__global__ void wprep_kernel(const float* __restrict__ w, __nv_bfloat16* __restrict__ hi,
                             __nv_bfloat16* __restrict__ lo, int COUT, int CIN)
{
    int total = COUT * CIN * 9;
    for (int idx = blockIdx.x * blockDim.x + threadIdx.x; idx < total;
         idx += gridDim.x * blockDim.x) {
        int co = idx / (CIN * 9);
        int rem = idx - co * (CIN * 9);
        int ci = rem / 9, tap = rem - ci * 9;
        float v = w[idx];
        __nv_bfloat16 h = __float2bfloat16(v);
        __nv_bfloat16 l = __float2bfloat16(v - __bfloat162float(h));
        size_t d = (size_t)co * (CIN * 9) + tap * CIN + ci;
        hi[d] = h; lo[d] = l;
    }
}

// bevs NCHW fp32 -> NHWC hi/lo bf16.
__global__ void actsplit_kernel(const float* __restrict__ in,
                                __nv_bfloat16* __restrict__ oh,
                                __nv_bfloat16* __restrict__ ol)
{
    __shared__ float s[32][257];
    int n = blockIdx.x, c0 = blockIdx.y * 32;
    int tid = threadIdx.x;
#pragma unroll
    for (int it = 0; it < 32; it++)
        s[it][tid] = in[((size_t)n * 256 + c0 + it) * 256 + tid];
    __syncthreads();
    int ci = tid & 31, p0 = tid >> 5;
#pragma unroll
    for (int pp = 0; pp < 32; pp++) {
        int pix = p0 + pp * 8;
        float v = s[ci][pix];
        __nv_bfloat16 h = __float2bfloat16(v);
        __nv_bfloat16 l = __float2bfloat16(v - __bfloat162float(h));
        size_t o = ((size_t)n * 256 + pix) * 256 + c0 + ci;
        oh[o] = h; ol[o] = l;
    }
}

// ---------------------------------------------------------------------------
// Implicit-GEMM conv3x3 (pad=1) + affine + ReLU, split-bf16 mma.sync.
// K-chunks of 64 (144B pitch, conflict-free ldmatrix), STAGES circular
// cp.async pipeline with ONE __syncthreads per chunk.
// MTILE=128: 4 m-warps x 2 n-warps.  MTILE=64: 2 m-warps x 4 n-warps.
// ---------------------------------------------------------------------------
static constexpr int SPB = 144;  // smem row pitch bytes (64 bf16 + 16B pad)

template <int CIN, int COUT, int HIN, int WIN, int STRIDE, int OUTMODE,
          int MTILE, int STAGES, int MINCTA>
__global__ void __launch_bounds__(256, MINCTA)
convMMA_kernel(const __nv_bfloat16* __restrict__ aH, const __nv_bfloat16* __restrict__ aL,
               const __nv_bfloat16* __restrict__ wH, const __nv_bfloat16* __restrict__ wL,
               const float* __restrict__ scale, const float* __restrict__ shift,
               __nv_bfloat16* __restrict__ oH, __nv_bfloat16* __restrict__ oL,
               float* __restrict__ oF)
{
    constexpr int HO   = (HIN - 1) / STRIDE + 1;
    constexpr int WO   = (WIN - 1) / STRIDE + 1;
    constexpr int MPIX = HO * WO;
    constexpr int NIMG = (MPIX >= MTILE) ? 1 : (MTILE / MPIX);
    constexpr int NT   = COUT / 128;
    constexpr int KTOT = 9 * CIN;
    constexpr int CPT  = CIN / 64;       // K-chunks per tap
    constexpr int NCH  = 9 * CPT;
    constexpr int MW   = MTILE / 32;     // m-warps
    constexpr int NW   = 8 / MW;         // n-warps
    constexpr int NCPW = 128 / NW;       // cout per warp
    constexpr int NT2  = NCPW / 16;
    constexpr int STB  = (MTILE + 128) * 2 * SPB;   // stage bytes
    constexpr int A_LO = MTILE * SPB;
    constexpr int B_HI = MTILE * 2 * SPB;
    constexpr int B_LO = B_HI + 128 * SPB;
    constexpr int RT   = (MTILE + 128) * 16;        // cp16 transfers per stage

    extern __shared__ char smem[];
    const uint32_t sb = smem_to_u32(smem);

    const int tid = threadIdx.x, wid = tid >> 5, lane = tid & 31;
    const int mt  = blockIdx.x / NT;
    const int co0 = (blockIdx.x % NT) * 128;
    const int n0  = blockIdx.y * NIMG;
    const int wm  = wid % MW;
    const int wn  = wid / MW;

    auto issue = [&](int c) {
        const uint32_t st = sb + (uint32_t)(c % STAGES) * STB;
        const int tap = c / CPT;
        const int ci0 = (c - tap * CPT) * 64;
        const int dy = tap / 3 - 1, dx = tap % 3 - 1;
#pragma unroll
        for (int i = tid; i < RT; i += 256) {
            const int row  = i >> 4;
            const int seg  = i & 7;
            const int half = (i >> 3) & 1;
            if (row < MTILE) {
                int g = mt * MTILE + row;
                int img = g / MPIX, pix = g % MPIX;
                int oh = pix / WO, ow = pix - oh * WO;
                int ih = oh * STRIDE + dy, iw = ow * STRIDE + dx;
                bool v = ((unsigned)ih < (unsigned)HIN) && ((unsigned)iw < (unsigned)WIN);
                int ihs = v ? ih : 0, iws = v ? iw : 0;
                size_t aoff = (((size_t)(n0 + img) * HIN + ihs) * WIN + iws) * CIN
                              + ci0 + seg * 8;
                uint32_t ad = st + (uint32_t)half * A_LO + (uint32_t)row * SPB + seg * 16;
                cp16(ad, (half ? aL : aH) + aoff, v);
            } else {
                int r2 = row - MTILE;
                size_t woff = (size_t)(co0 + r2) * KTOT + (size_t)c * 64 + seg * 8;
                uint32_t bd = st + B_HI + (uint32_t)half * (128 * SPB)
                              + (uint32_t)r2 * SPB + seg * 16;
                cp16(bd, (half ? wL : wH) + woff, true);
            }
        }
        CP_COMMIT();
    };

    float acc[2][NT2 * 2][4];
#pragma unroll
    for (int a = 0; a < 2; a++)
#pragma unroll
        for (int b = 0; b < NT2 * 2; b++)
#pragma unroll
            for (int c = 0; c < 4; c++) acc[a][b][c] = 0.f;

    // prologue: STAGES-1 chunks in flight
#pragma unroll
    for (int p = 0; p < STAGES - 1; p++) issue(p);

    for (int c = 0; c < NCH; c++) {
        // chunk c complete (leave STAGES-2 groups in flight)
        asm volatile("cp.async.wait_group %0;" :: "n"(STAGES - 2) : "memory");
        __syncthreads();
        if (c + STAGES - 1 < NCH) issue(c + STAGES - 1);
        else CP_COMMIT();

        const uint32_t st  = sb + (uint32_t)(c % STAGES) * STB;
        const uint32_t sAh = st, sAl = st + A_LO, sBh = st + B_HI, sBl = st + B_LO;
#pragma unroll
        for (int ks = 0; ks < 4; ks++) {
            const uint32_t acol = (uint32_t)ks * 32u + ((lane >> 4) << 4);
            uint32_t ah[2][4], al2[2][4];
#pragma unroll
            for (int m2 = 0; m2 < 2; m2++) {
                uint32_t arow = (uint32_t)(wm * 32 + m2 * 16 + (lane & 15));
                ldsm_x4(ah[m2],  sAh + arow * SPB + acol);
                ldsm_x4(al2[m2], sAl + arow * SPB + acol);
            }
#pragma unroll
            for (int nt2 = 0; nt2 < NT2; nt2++) {
                uint32_t brow = (uint32_t)(wn * NCPW + nt2 * 16 +
                                           ((lane >> 4) << 3) + (lane & 7));
                uint32_t bcol = (uint32_t)ks * 32u + (((lane >> 3) & 1) << 4);
                uint32_t bh[4], bl4[4];
                ldsm_x4(bh, sBh + brow * SPB + bcol);
#pragma unroll
                for (int m2 = 0; m2 < 2; m2++) {
                    mma_bf16(acc[m2][nt2 * 2],     ah[m2], bh[0], bh[1]);
                    mma_bf16(acc[m2][nt2 * 2 + 1], ah[m2], bh[2], bh[3]);
                }
                ldsm_x4(bl4, sBl + brow * SPB + bcol);
#pragma unroll
                for (int m2 = 0; m2 < 2; m2++) {
                    mma_bf16(acc[m2][nt2 * 2],     ah[m2], bl4[0], bl4[1]);
                    mma_bf16(acc[m2][nt2 * 2 + 1], ah[m2], bl4[2], bl4[3]);
                    mma_bf16(acc[m2][nt2 * 2],     al2[m2], bh[0], bh[1]);
                    mma_bf16(acc[m2][nt2 * 2 + 1], al2[m2], bh[2], bh[3]);
                }
            }
        }
    }

    if (OUTMODE == 0) {
        // ---- NHWC hi/lo epilogue: direct from fragments ----
#pragma unroll
        for (int m2 = 0; m2 < 2; m2++) {
            int mA = wm * 32 + m2 * 16 + (lane >> 2);
            int gA = mt * MTILE + mA;
            int gB = gA + 8;
            size_t rowA = ((size_t)(n0 + gA / MPIX) * MPIX + gA % MPIX) * COUT;
            size_t rowB = ((size_t)(n0 + gB / MPIX) * MPIX + gB % MPIX) * COUT;
#pragma unroll
            for (int j = 0; j < NT2 * 2; j++) {
                int co = co0 + wn * NCPW + j * 8 + (lane & 3) * 2;
                float s0 = __ldg(scale + co), s1 = __ldg(scale + co + 1);
                float t0 = __ldg(shift + co), t1 = __ldg(shift + co + 1);
                float v0 = fmaxf(fmaf(acc[m2][j][0], s0, t0), 0.f);
                float v1 = fmaxf(fmaf(acc[m2][j][1], s1, t1), 0.f);
                float v2 = fmaxf(fmaf(acc[m2][j][2], s0, t0), 0.f);
                float v3 = fmaxf(fmaf(acc[m2][j][3], s1, t1), 0.f);
                __nv_bfloat16 h0 = __float2bfloat16(v0), h1 = __float2bfloat16(v1);
                __nv_bfloat16 h2 = __float2bfloat16(v2), h3 = __float2bfloat16(v3);
                __nv_bfloat16 l0 = __float2bfloat16(v0 - __bfloat162float(h0));
                __nv_bfloat16 l1 = __float2bfloat16(v1 - __bfloat162float(h1));
                __nv_bfloat16 l2 = __float2bfloat16(v2 - __bfloat162float(h2));
                __nv_bfloat16 l3 = __float2bfloat16(v3 - __bfloat162float(h3));
                *reinterpret_cast<uint32_t*>(oH + rowA + co) = pack_bf2(h0, h1);
                *reinterpret_cast<uint32_t*>(oL + rowA + co) = pack_bf2(l0, l1);
                *reinterpret_cast<uint32_t*>(oH + rowB + co) = pack_bf2(h2, h3);
                *reinterpret_cast<uint32_t*>(oL + rowB + co) = pack_bf2(l2, l3);
            }
        }
    } else {
        // ---- CHW fp32 epilogue (conv5 -> feats): transpose via smem ----
        constexpr int OPITCH = MTILE + 4;
        float* sOut = reinterpret_cast<float*>(smem);
        __syncthreads();
#pragma unroll
        for (int m2 = 0; m2 < 2; m2++) {
#pragma unroll
            for (int j = 0; j < NT2 * 2; j++) {
                int m = wm * 32 + m2 * 16 + (lane >> 2);
                int nn = wn * NCPW + j * 8 + (lane & 3) * 2;
                sOut[(size_t)nn * OPITCH + m]           = acc[m2][j][0];
                sOut[(size_t)(nn + 1) * OPITCH + m]     = acc[m2][j][1];
                sOut[(size_t)nn * OPITCH + m + 8]       = acc[m2][j][2];
                sOut[(size_t)(nn + 1) * OPITCH + m + 8] = acc[m2][j][3];
            }
        }
        __syncthreads();
        int row = tid >> 1, half = tid & 1;
        int co = co0 + row;
        float s = __ldg(scale + co), t = __ldg(shift + co);
#pragma unroll
        for (int q = 0; q < MTILE / 8; q++) {
            int m = half * (MTILE / 2) + q * 4;
            float4 v = *reinterpret_cast<float4*>(&sOut[(size_t)row * OPITCH + m]);
            v.x = fmaxf(fmaf(v.x, s, t), 0.f);
            v.y = fmaxf(fmaf(v.y, s, t), 0.f);
            v.z = fmaxf(fmaf(v.z, s, t), 0.f);
            v.w = fmaxf(fmaf(v.w, s, t), 0.f);
            int g = mt * MTILE + m;
            int img = g / MPIX, pix = g % MPIX;
            *reinterpret_cast<float4*>(
                &oF[((size_t)(n0 + img) * COUT + co) * MPIX + pix]) = v;
        }
    }
}

// ---------------------------------------------------------------------------
// Warp-tile GEMV: each warp computes a 4m x 8n tile of Y = X.W^T + b.
// ---------------------------------------------------------------------------
__global__ void warptile_kernel(const float* __restrict__ X, const float* __restrict__ W,
                                const float* __restrict__ bias, float* __restrict__ Y,
                                int M, int N, int K, int doRelu)
{
    int gw   = (blockIdx.x * blockDim.x + threadIdx.x) >> 5;
    int lane = threadIdx.x & 31;
    int nW = N >> 3;
    int mtile = gw / nW, ntile = gw - mtile * nW;
    if (mtile * 4 >= M) return;
    const float* x0 = X + (size_t)(mtile * 4) * K;
    const float* w0 = W + (size_t)(ntile * 8) * K;
    float acc[4][8];
#pragma unroll
    for (int i = 0; i < 4; i++)
#pragma unroll
        for (int j = 0; j < 8; j++) acc[i][j] = 0.f;
    for (int k = lane; k < K; k += 32) {
        float xv[4], wv[8];
#pragma unroll
        for (int i = 0; i < 4; i++) xv[i] = x0[(size_t)i * K + k];
#pragma unroll
        for (int j = 0; j < 8; j++) wv[j] = w0[(size_t)j * K + k];
#pragma unroll
        for (int i = 0; i < 4; i++)
#pragma unroll
            for (int j = 0; j < 8; j++) acc[i][j] = fmaf(xv[i], wv[j], acc[i][j]);
    }
#pragma unroll
    for (int o = 16; o; o >>= 1)
#pragma unroll
        for (int i = 0; i < 4; i++)
#pragma unroll
            for (int j = 0; j < 8; j++)
                acc[i][j] += __shfl_xor_sync(0xffffffffu, acc[i][j], o);
    int i = lane >> 3, j = lane & 7;
    float v = acc[i][j] + bias[ntile * 8 + j];
    if (doRelu) v = fmaxf(v, 0.f);
    Y[(size_t)(mtile * 4 + i) * N + ntile * 8 + j] = v;
}

// ---------------------------------------------------------------------------
// Attention + softmax -> fuse weights; final fuse.
// ---------------------------------------------------------------------------
__global__ void attn_kernel(const float* __restrict__ keys, const float* __restrict__ qq,
                            float* __restrict__ wf)
{
    int b = blockIdx.x;
    __shared__ float sA[5][5];
    int warp = threadIdx.x >> 5, lane = threadIdx.x & 31;
    for (int e = warp; e < 25; e += 8) {
        int i = e / 5, j = e - i * 5;
        const float4* kr = (const float4*)(keys + (size_t)(i * 32 + b) * 1024);
        const float4* qr = (const float4*)(qq + (size_t)(j * 32 + b) * 1024);
        float acc = 0.f;
        for (int k = lane; k < 256; k += 32) {
            float4 a = kr[k], c = qr[k];
            acc += a.x * c.x + a.y * c.y + a.z * c.z + a.w * c.w;
        }
#pragma unroll
        for (int o = 16; o; o >>= 1) acc += __shfl_xor_sync(0xffffffffu, acc, o);
        if (lane == 0) sA[i][j] = acc;
    }
    __syncthreads();
    if (threadIdx.x == 0) {
        float w[5] = {0.f, 0.f, 0.f, 0.f, 0.f};
        for (int j = 0; j < 5; j++) {
            float dd[4], mx = -1e30f;
            for (int r = 0; r < 4; r++) {
                dd[r] = (j > r) ? sA[r][j] : sA[r + 1][j];
                mx = fmaxf(mx, dd[r]);
            }
            float s = 0.f;
            for (int r = 0; r < 4; r++) { dd[r] = expf(dd[r] - mx); s += dd[r]; }
            float inv = 1.f / s;
            for (int r = 0; r < 4; r++) {
                int i = (j > r) ? r : r + 1;
                w[i] += dd[r] * inv;
            }
        }
        for (int i = 0; i < 5; i++) wf[b * 5 + i] = w[i] * 0.2f;
    }
}

__global__ void fuse_kernel(const float* __restrict__ bevs, const float* __restrict__ wf,
                            float* __restrict__ out)
{
    const int CHW = 256 * 16 * 16;
    int idx = blockIdx.x * blockDim.x + threadIdx.x;
    if (idx >= 32 * CHW) return;
    int b   = idx / CHW;
    int chw = idx - b * CHW;
    const float* base = bevs + ((size_t)b * 5) * CHW + chw;
    float acc = 0.f;
#pragma unroll
    for (int k = 0; k < 5; k++) acc += wf[b * 5 + k] * base[(size_t)k * CHW];
    out[idx] = acc;
}

// ---------------------------------------------------------------------------
extern "C" void kernel_launch(void* const* d_in, const int* in_sizes, int n_in,
                              void* d_out, int out_size)
{
    (void)in_sizes; (void)n_in; (void)out_size;
    const float* bevs = (const float*)d_in[0];
    const float *cw[5], *cs[5], *ct[5];
    for (int i = 0; i < 5; i++) {
        cw[i] = (const float*)d_in[1 + 3 * i];
        cs[i] = (const float*)d_in[2 + 3 * i];
        ct[i] = (const float*)d_in[3 + 3 * i];
    }
    const float* kw1 = (const float*)d_in[16]; const float* kb1 = (const float*)d_in[17];
    const float* kw2 = (const float*)d_in[18]; const float* kb2 = (const float*)d_in[19];
    const float* kw3 = (const float*)d_in[20]; const float* kb3 = (const float*)d_in[21];
    const float* qw1 = (const float*)d_in[22]; const float* qb1 = (const float*)d_in[23];
    const float* qw2 = (const float*)d_in[24]; const float* qb2 = (const float*)d_in[25];
    const float* qw3 = (const float*)d_in[26]; const float* qb3 = (const float*)d_in[27];
    const float* aw  = (const float*)d_in[28]; const float* ab  = (const float*)d_in[29];
    float* out = (float*)d_out;

    __nv_bfloat16 *a0h, *a0l, *b1h, *b1l, *b2h, *b2l, *b3h, *b3l, *b4h, *b4l;
    cudaGetSymbolAddress((void**)&a0h, g_a0h); cudaGetSymbolAddress((void**)&a0l, g_a0l);
    cudaGetSymbolAddress((void**)&b1h, g_b1h); cudaGetSymbolAddress((void**)&b1l, g_b1l);
    cudaGetSymbolAddress((void**)&b2h, g_b2h); cudaGetSymbolAddress((void**)&b2l, g_b2l);
    cudaGetSymbolAddress((void**)&b3h, g_b3h); cudaGetSymbolAddress((void**)&b3l, g_b3l);
    cudaGetSymbolAddress((void**)&b4h, g_b4h); cudaGetSymbolAddress((void**)&b4l, g_b4l);
    float *feat, *m1, *m2, *keys, *qrys, *qq, *wf;
    cudaGetSymbolAddress((void**)&feat, g_feat);
    cudaGetSymbolAddress((void**)&m1, g_m1);
    cudaGetSymbolAddress((void**)&m2, g_m2);
    cudaGetSymbolAddress((void**)&keys, g_keys);
    cudaGetSymbolAddress((void**)&qrys, g_qrys);
    cudaGetSymbolAddress((void**)&qq, g_qq);
    cudaGetSymbolAddress((void**)&wf, g_wf);
    __nv_bfloat16 *w1h, *w1l, *w2h, *w2l, *w3h, *w3l, *w4h, *w4l, *w5h, *w5l;
    cudaGetSymbolAddress((void**)&w1h, g_w1h); cudaGetSymbolAddress((void**)&w1l, g_w1l);
    cudaGetSymbolAddress((void**)&w2h, g_w2h); cudaGetSymbolAddress((void**)&w2l, g_w2l);
    cudaGetSymbolAddress((void**)&w3h, g_w3h); cudaGetSymbolAddress((void**)&w3l, g_w3l);
    cudaGetSymbolAddress((void**)&w4h, g_w4h); cudaGetSymbolAddress((void**)&w4l, g_w4l);
    cudaGetSymbolAddress((void**)&w5h, g_w5h); cudaGetSymbolAddress((void**)&w5l, g_w5l);

    // stage bytes: MTILE128 -> 73728; MTILE64 -> 55296
    constexpr int SMEM_L12 = 3 * 73728;   // 221184, 1 CTA/SM
    constexpr int SMEM_S   = 2 * 55296;   // 110592, 2 CTAs/SM

    cudaFuncSetAttribute(convMMA_kernel<256, 512, 16, 16, 1, 0, 128, 3, 1>,
                         cudaFuncAttributeMaxDynamicSharedMemorySize, SMEM_L12);
    cudaFuncSetAttribute(convMMA_kernel<512, 256, 16, 16, 1, 0, 128, 3, 1>,
                         cudaFuncAttributeMaxDynamicSharedMemorySize, SMEM_L12);
    cudaFuncSetAttribute(convMMA_kernel<256, 256, 16, 16, 2, 0, 64, 2, 2>,
                         cudaFuncAttributeMaxDynamicSharedMemorySize, SMEM_S);
    cudaFuncSetAttribute(convMMA_kernel<256, 256, 8, 8, 1, 0, 64, 2, 2>,
                         cudaFuncAttributeMaxDynamicSharedMemorySize, SMEM_S);
    cudaFuncSetAttribute(convMMA_kernel<256, 256, 8, 8, 2, 1, 64, 2, 2>,
                         cudaFuncAttributeMaxDynamicSharedMemorySize, SMEM_S);

    // prep: weight splits + bevs NCHW->NHWC split
    wprep_kernel<<<512, 256>>>(cw[0], w1h, w1l, 512, 256);
    wprep_kernel<<<512, 256>>>(cw[1], w2h, w2l, 256, 512);
    wprep_kernel<<<512, 256>>>(cw[2], w3h, w3l, 256, 256);
    wprep_kernel<<<512, 256>>>(cw[3], w4h, w4l, 256, 256);
    wprep_kernel<<<512, 256>>>(cw[4], w5h, w5l, 256, 256);
    actsplit_kernel<<<dim3(160, 8), 256>>>(bevs, a0h, a0l);

    // conv stack
    convMMA_kernel<256, 512, 16, 16, 1, 0, 128, 3, 1><<<dim3(8, 160), 256, SMEM_L12>>>(
        a0h, a0l, w1h, w1l, cs[0], ct[0], b1h, b1l, nullptr);
    convMMA_kernel<512, 256, 16, 16, 1, 0, 128, 3, 1><<<dim3(4, 160), 256, SMEM_L12>>>(
        b1h, b1l, w2h, w2l, cs[1], ct[1], b2h, b2l, nullptr);
    convMMA_kernel<256, 256, 16, 16, 2, 0, 64, 2, 2><<<dim3(2, 160), 256, SMEM_S>>>(
        b2h, b2l, w3h, w3l, cs[2], ct[2], b3h, b3l, nullptr);
    convMMA_kernel<256, 256, 8, 8, 1, 0, 64, 2, 2><<<dim3(2, 160), 256, SMEM_S>>>(
        b3h, b3l, w4h, w4l, cs[3], ct[3], b4h, b4l, nullptr);
    convMMA_kernel<256, 256, 8, 8, 2, 1, 64, 2, 2><<<dim3(2, 40), 256, SMEM_S>>>(
        b4h, b4l, w5h, w5l, cs[4], ct[4], nullptr, nullptr, feat);

    // MLPs + projection
    auto wt = [&](const float* X, const float* W, const float* B, float* Y,
                  int M, int N, int K, int relu) {
        int warps = (M / 4) * (N / 8);
        warptile_kernel<<<(warps + 7) / 8, 256>>>(X, W, B, Y, M, N, K, relu);
    };
    wt(feat, kw1, kb1, m1,   160,  256, 4096, 1);
    wt(m1,   kw2, kb2, m2,   160,  128,  256, 1);
    wt(m2,   kw3, kb3, keys, 160, 1024,  128, 0);
    wt(feat, qw1, qb1, m1,   160,  256, 4096, 1);
    wt(m1,   qw2, qb2, m2,   160,  128,  256, 1);
    wt(m2,   qw3, qb3, qrys, 160,   32,  128, 0);
    wt(qrys, aw,  ab,  qq,   160, 1024,   32, 0);

    attn_kernel<<<32, 256>>>(keys, qq, wf);
    fuse_kernel<<<(32 * 256 * 16 * 16 + 255) / 256, 256>>>(bevs, wf, out);
}

// round 8
// speedup vs baseline: 1.2043x; 1.1002x over previous
#include <cuda_runtime.h>
#include <cuda_bf16.h>
#include <cstdint>
#include <cstddef>

// ===========================================================================
// Who2com forward — split-bf16 mma.sync implicit-GEMM convs.
// R8: merged prep (1 launch) so conv2 lands at ncu's captured launch index;
// fused k/q tail chains (warptile2); conv core identical to R7.
// ===========================================================================

__device__ __forceinline__ uint32_t smem_to_u32(const void* p) {
    uint32_t a;
    asm("{ .reg .u64 t; cvta.to.shared.u64 t, %1; cvt.u32.u64 %0, t; }"
        : "=r"(a) : "l"(p));
    return a;
}
__device__ __forceinline__ void ldsm_x4(uint32_t (&r)[4], uint32_t addr) {
    asm volatile("ldmatrix.sync.aligned.m8n8.x4.shared.b16 {%0,%1,%2,%3}, [%4];"
                 : "=r"(r[0]), "=r"(r[1]), "=r"(r[2]), "=r"(r[3]) : "r"(addr));
}
__device__ __forceinline__ void mma_bf16(float (&d)[4], const uint32_t (&a)[4],
                                         uint32_t b0, uint32_t b1) {
    asm volatile(
        "mma.sync.aligned.m16n8k16.row.col.f32.bf16.bf16.f32 "
        "{%0,%1,%2,%3}, {%4,%5,%6,%7}, {%8,%9}, {%0,%1,%2,%3};"
        : "+f"(d[0]), "+f"(d[1]), "+f"(d[2]), "+f"(d[3])
        : "r"(a[0]), "r"(a[1]), "r"(a[2]), "r"(a[3]), "r"(b0), "r"(b1));
}
__device__ __forceinline__ uint32_t pack_bf2(__nv_bfloat16 a, __nv_bfloat16 b) {
    __nv_bfloat162 t = __halves2bfloat162(a, b);
    return *reinterpret_cast<uint32_t*>(&t);
}
__device__ __forceinline__ void cp16(uint32_t dst, const void* src, bool v) {
    asm volatile("cp.async.cg.shared.global [%0], [%1], 16, %2;"
                 :: "r"(dst), "l"(src), "r"(v ? 16u : 0u) : "memory");
}
#define CP_COMMIT() asm volatile("cp.async.commit_group;" ::: "memory")

// ---------------------------------------------------------------------------
// Scratch
// ---------------------------------------------------------------------------
__device__ __align__(16) __nv_bfloat16 g_a0h[(size_t)160 * 256 * 256];
__device__ __align__(16) __nv_bfloat16 g_a0l[(size_t)160 * 256 * 256];
__device__ __align__(16) __nv_bfloat16 g_b1h[(size_t)160 * 256 * 512];
__device__ __align__(16) __nv_bfloat16 g_b1l[(size_t)160 * 256 * 512];
__device__ __align__(16) __nv_bfloat16 g_b2h[(size_t)160 * 256 * 256];
__device__ __align__(16) __nv_bfloat16 g_b2l[(size_t)160 * 256 * 256];
__device__ __align__(16) __nv_bfloat16 g_b3h[(size_t)160 * 64 * 256];
__device__ __align__(16) __nv_bfloat16 g_b3l[(size_t)160 * 64 * 256];
__device__ __align__(16) __nv_bfloat16 g_b4h[(size_t)160 * 64 * 256];
__device__ __align__(16) __nv_bfloat16 g_b4l[(size_t)160 * 64 * 256];
__device__ float g_feat[(size_t)160 * 4096];
__device__ float g_m1k[160 * 256], g_m1q[160 * 256];
__device__ float g_m2k[160 * 128], g_m2q[160 * 128];
__device__ float g_keys[160 * 1024];
__device__ float g_qrys[160 * 32];
__device__ float g_qq[160 * 1024];
__device__ float g_wf[32 * 5];
__device__ __align__(16) __nv_bfloat16 g_w1h[512 * 2304], g_w1l[512 * 2304];
__device__ __align__(16) __nv_bfloat16 g_w2h[256 * 4608], g_w2l[256 * 4608];
__device__ __align__(16) __nv_bfloat16 g_w3h[256 * 2304], g_w3l[256 * 2304];
__device__ __align__(16) __nv_bfloat16 g_w4h[256 * 2304], g_w4l[256 * 2304];
__device__ __align__(16) __nv_bfloat16 g_w5h[256 * 2304], g_w5l[256 * 2304];

// ---------------------------------------------------------------------------
// Merged weight prep: all 5 conv layers in one launch.
// src[co][ci][kh][kw] -> hi/lo bf16 at [co][(kh*3+kw)*CIN + ci]
// ---------------------------------------------------------------------------
struct WPrepDesc {
    const float* src;
    __nv_bfloat16* hi;
    __nv_bfloat16* lo;
    int cin;
    int total;   // cout*cin*9
    int base;    // exclusive prefix of totals
};

__global__ void wprep_all_kernel(WPrepDesc d0, WPrepDesc d1, WPrepDesc d2,
                                 WPrepDesc d3, WPrepDesc d4, int grand)
{
    WPrepDesc ds[5] = {d0, d1, d2, d3, d4};
    for (int g = blockIdx.x * blockDim.x + threadIdx.x; g < grand;
         g += gridDim.x * blockDim.x) {
        int li = 0;
#pragma unroll
        for (int t = 1; t < 5; t++)
            if (g >= ds[t].base) li = t;
        const WPrepDesc& d = ds[li];
        int idx = g - d.base;
        int cin9 = d.cin * 9;
        int co = idx / cin9;
        int rem = idx - co * cin9;
        int ci = rem / 9, tap = rem - ci * 9;
        float v = d.src[idx];
        __nv_bfloat16 h = __float2bfloat16(v);
        __nv_bfloat16 l = __float2bfloat16(v - __bfloat162float(h));
        size_t dd = (size_t)co * cin9 + tap * d.cin + ci;
        d.hi[dd] = h; d.lo[dd] = l;
    }
}

// bevs NCHW fp32 -> NHWC hi/lo bf16.
__global__ void actsplit_kernel(const float* __restrict__ in,
                                __nv_bfloat16* __restrict__ oh,
                                __nv_bfloat16* __restrict__ ol)
{
    __shared__ float s[32][257];
    int n = blockIdx.x, c0 = blockIdx.y * 32;
    int tid = threadIdx.x;
#pragma unroll
    for (int it = 0; it < 32; it++)
        s[it][tid] = in[((size_t)n * 256 + c0 + it) * 256 + tid];
    __syncthreads();
    int ci = tid & 31, p0 = tid >> 5;
#pragma unroll
    for (int pp = 0; pp < 32; pp++) {
        int pix = p0 + pp * 8;
        float v = s[ci][pix];
        __nv_bfloat16 h = __float2bfloat16(v);
        __nv_bfloat16 l = __float2bfloat16(v - __bfloat162float(h));
        size_t o = ((size_t)n * 256 + pix) * 256 + c0 + ci;
        oh[o] = h; ol[o] = l;
    }
}

// ---------------------------------------------------------------------------
// Implicit-GEMM conv3x3 (pad=1) + affine + ReLU, split-bf16 mma.sync.
// K-chunks of 64 (144B pitch), circular STAGES cp.async pipeline, one
// __syncthreads per chunk.  (identical to R7 core)
// ---------------------------------------------------------------------------
static constexpr int SPB = 144;

template <int CIN, int COUT, int HIN, int WIN, int STRIDE, int OUTMODE,
          int MTILE, int STAGES, int MINCTA>
__global__ void __launch_bounds__(256, MINCTA)
convMMA_kernel(const __nv_bfloat16* __restrict__ aH, const __nv_bfloat16* __restrict__ aL,
               const __nv_bfloat16* __restrict__ wH, const __nv_bfloat16* __restrict__ wL,
               const float* __restrict__ scale, const float* __restrict__ shift,
               __nv_bfloat16* __restrict__ oH, __nv_bfloat16* __restrict__ oL,
               float* __restrict__ oF)
{
    constexpr int HO   = (HIN - 1) / STRIDE + 1;
    constexpr int WO   = (WIN - 1) / STRIDE + 1;
    constexpr int MPIX = HO * WO;
    constexpr int NIMG = (MPIX >= MTILE) ? 1 : (MTILE / MPIX);
    constexpr int NT   = COUT / 128;
    constexpr int KTOT = 9 * CIN;
    constexpr int CPT  = CIN / 64;
    constexpr int NCH  = 9 * CPT;
    constexpr int MW   = MTILE / 32;
    constexpr int NW   = 8 / MW;
    constexpr int NCPW = 128 / NW;
    constexpr int NT2  = NCPW / 16;
    constexpr int STB  = (MTILE + 128) * 2 * SPB;
    constexpr int A_LO = MTILE * SPB;
    constexpr int B_HI = MTILE * 2 * SPB;
    constexpr int B_LO = B_HI + 128 * SPB;
    constexpr int RT   = (MTILE + 128) * 16;

    extern __shared__ char smem[];
    const uint32_t sb = smem_to_u32(smem);

    const int tid = threadIdx.x, wid = tid >> 5, lane = tid & 31;
    const int mt  = blockIdx.x / NT;
    const int co0 = (blockIdx.x % NT) * 128;
    const int n0  = blockIdx.y * NIMG;
    const int wm  = wid % MW;
    const int wn  = wid / MW;

    auto issue = [&](int c) {
        const uint32_t st = sb + (uint32_t)(c % STAGES) * STB;
        const int tap = c / CPT;
        const int ci0 = (c - tap * CPT) * 64;
        const int dy = tap / 3 - 1, dx = tap % 3 - 1;
#pragma unroll
        for (int i = tid; i < RT; i += 256) {
            const int row  = i >> 4;
            const int seg  = i & 7;
            const int half = (i >> 3) & 1;
            if (row < MTILE) {
                int g = mt * MTILE + row;
                int img = g / MPIX, pix = g % MPIX;
                int oh = pix / WO, ow = pix - oh * WO;
                int ih = oh * STRIDE + dy, iw = ow * STRIDE + dx;
                bool v = ((unsigned)ih < (unsigned)HIN) && ((unsigned)iw < (unsigned)WIN);
                int ihs = v ? ih : 0, iws = v ? iw : 0;
                size_t aoff = (((size_t)(n0 + img) * HIN + ihs) * WIN + iws) * CIN
                              + ci0 + seg * 8;
                uint32_t ad = st + (uint32_t)half * A_LO + (uint32_t)row * SPB + seg * 16;
                cp16(ad, (half ? aL : aH) + aoff, v);
            } else {
                int r2 = row - MTILE;
                size_t woff = (size_t)(co0 + r2) * KTOT + (size_t)c * 64 + seg * 8;
                uint32_t bd = st + B_HI + (uint32_t)half * (128 * SPB)
                              + (uint32_t)r2 * SPB + seg * 16;
                cp16(bd, (half ? wL : wH) + woff, true);
            }
        }
        CP_COMMIT();
    };

    float acc[2][NT2 * 2][4];
#pragma unroll
    for (int a = 0; a < 2; a++)
#pragma unroll
        for (int b = 0; b < NT2 * 2; b++)
#pragma unroll
            for (int c = 0; c < 4; c++) acc[a][b][c] = 0.f;

#pragma unroll
    for (int p = 0; p < STAGES - 1; p++) issue(p);

    for (int c = 0; c < NCH; c++) {
        asm volatile("cp.async.wait_group %0;" :: "n"(STAGES - 2) : "memory");
        __syncthreads();
        if (c + STAGES - 1 < NCH) issue(c + STAGES - 1);
        else CP_COMMIT();

        const uint32_t st  = sb + (uint32_t)(c % STAGES) * STB;
        const uint32_t sAh = st, sAl = st + A_LO, sBh = st + B_HI, sBl = st + B_LO;
#pragma unroll
        for (int ks = 0; ks < 4; ks++) {
            const uint32_t acol = (uint32_t)ks * 32u + ((lane >> 4) << 4);
            uint32_t ah[2][4], al2[2][4];
#pragma unroll
            for (int m2 = 0; m2 < 2; m2++) {
                uint32_t arow = (uint32_t)(wm * 32 + m2 * 16 + (lane & 15));
                ldsm_x4(ah[m2],  sAh + arow * SPB + acol);
                ldsm_x4(al2[m2], sAl + arow * SPB + acol);
            }
#pragma unroll
            for (int nt2 = 0; nt2 < NT2; nt2++) {
                uint32_t brow = (uint32_t)(wn * NCPW + nt2 * 16 +
                                           ((lane >> 4) << 3) + (lane & 7));
                uint32_t bcol = (uint32_t)ks * 32u + (((lane >> 3) & 1) << 4);
                uint32_t bh[4], bl4[4];
                ldsm_x4(bh, sBh + brow * SPB + bcol);
#pragma unroll
                for (int m2 = 0; m2 < 2; m2++) {
                    mma_bf16(acc[m2][nt2 * 2],     ah[m2], bh[0], bh[1]);
                    mma_bf16(acc[m2][nt2 * 2 + 1], ah[m2], bh[2], bh[3]);
                }
                ldsm_x4(bl4, sBl + brow * SPB + bcol);
#pragma unroll
                for (int m2 = 0; m2 < 2; m2++) {
                    mma_bf16(acc[m2][nt2 * 2],     ah[m2], bl4[0], bl4[1]);
                    mma_bf16(acc[m2][nt2 * 2 + 1], ah[m2], bl4[2], bl4[3]);
                    mma_bf16(acc[m2][nt2 * 2],     al2[m2], bh[0], bh[1]);
                    mma_bf16(acc[m2][nt2 * 2 + 1], al2[m2], bh[2], bh[3]);
                }
            }
        }
    }

    if (OUTMODE == 0) {
#pragma unroll
        for (int m2 = 0; m2 < 2; m2++) {
            int mA = wm * 32 + m2 * 16 + (lane >> 2);
            int gA = mt * MTILE + mA;
            int gB = gA + 8;
            size_t rowA = ((size_t)(n0 + gA / MPIX) * MPIX + gA % MPIX) * COUT;
            size_t rowB = ((size_t)(n0 + gB / MPIX) * MPIX + gB % MPIX) * COUT;
#pragma unroll
            for (int j = 0; j < NT2 * 2; j++) {
                int co = co0 + wn * NCPW + j * 8 + (lane & 3) * 2;
                float s0 = __ldg(scale + co), s1 = __ldg(scale + co + 1);
                float t0 = __ldg(shift + co), t1 = __ldg(shift + co + 1);
                float v0 = fmaxf(fmaf(acc[m2][j][0], s0, t0), 0.f);
                float v1 = fmaxf(fmaf(acc[m2][j][1], s1, t1), 0.f);
                float v2 = fmaxf(fmaf(acc[m2][j][2], s0, t0), 0.f);
                float v3 = fmaxf(fmaf(acc[m2][j][3], s1, t1), 0.f);
                __nv_bfloat16 h0 = __float2bfloat16(v0), h1 = __float2bfloat16(v1);
                __nv_bfloat16 h2 = __float2bfloat16(v2), h3 = __float2bfloat16(v3);
                __nv_bfloat16 l0 = __float2bfloat16(v0 - __bfloat162float(h0));
                __nv_bfloat16 l1 = __float2bfloat16(v1 - __bfloat162float(h1));
                __nv_bfloat16 l2 = __float2bfloat16(v2 - __bfloat162float(h2));
                __nv_bfloat16 l3 = __float2bfloat16(v3 - __bfloat162float(h3));
                *reinterpret_cast<uint32_t*>(oH + rowA + co) = pack_bf2(h0, h1);
                *reinterpret_cast<uint32_t*>(oL + rowA + co) = pack_bf2(l0, l1);
                *reinterpret_cast<uint32_t*>(oH + rowB + co) = pack_bf2(h2, h3);
                *reinterpret_cast<uint32_t*>(oL + rowB + co) = pack_bf2(l2, l3);
            }
        }
    } else {
        constexpr int OPITCH = MTILE + 4;
        float* sOut = reinterpret_cast<float*>(smem);
        __syncthreads();
#pragma unroll
        for (int m2 = 0; m2 < 2; m2++) {
#pragma unroll
            for (int j = 0; j < NT2 * 2; j++) {
                int m = wm * 32 + m2 * 16 + (lane >> 2);
                int nn = wn * NCPW + j * 8 + (lane & 3) * 2;
                sOut[(size_t)nn * OPITCH + m]           = acc[m2][j][0];
                sOut[(size_t)(nn + 1) * OPITCH + m]     = acc[m2][j][1];
                sOut[(size_t)nn * OPITCH + m + 8]       = acc[m2][j][2];
                sOut[(size_t)(nn + 1) * OPITCH + m + 8] = acc[m2][j][3];
            }
        }
        __syncthreads();
        int row = tid >> 1, half = tid & 1;
        int co = co0 + row;
        float s = __ldg(scale + co), t = __ldg(shift + co);
#pragma unroll
        for (int q = 0; q < MTILE / 8; q++) {
            int m = half * (MTILE / 2) + q * 4;
            float4 v = *reinterpret_cast<float4*>(&sOut[(size_t)row * OPITCH + m]);
            v.x = fmaxf(fmaf(v.x, s, t), 0.f);
            v.y = fmaxf(fmaf(v.y, s, t), 0.f);
            v.z = fmaxf(fmaf(v.z, s, t), 0.f);
            v.w = fmaxf(fmaf(v.w, s, t), 0.f);
            int g = mt * MTILE + m;
            int img = g / MPIX, pix = g % MPIX;
            *reinterpret_cast<float4*>(
                &oF[((size_t)(n0 + img) * COUT + co) * MPIX + pix]) = v;
        }
    }
}

// ---------------------------------------------------------------------------
// Warp-tile GEMV over TWO independent (X,W,b,Y,N) sets in one launch.
// Each warp computes a 4m x 8n tile.
// ---------------------------------------------------------------------------
__global__ void warptile2_kernel(const float* __restrict__ X1, const float* __restrict__ W1,
                                 const float* __restrict__ B1, float* __restrict__ Y1, int N1,
                                 const float* __restrict__ X2, const float* __restrict__ W2,
                                 const float* __restrict__ B2, float* __restrict__ Y2, int N2,
                                 int M, int K, int doRelu)
{
    int gw   = (blockIdx.x * blockDim.x + threadIdx.x) >> 5;
    int lane = threadIdx.x & 31;
    int nWtot = (N1 + N2) >> 3;
    int mtile = gw / nWtot, ntile = gw - mtile * nWtot;
    if (mtile * 4 >= M) return;
    const float *X, *W, *Bb;
    float* Y;
    int N, nt;
    if (ntile < (N1 >> 3)) { X = X1; W = W1; Bb = B1; Y = Y1; N = N1; nt = ntile; }
    else { X = X2; W = W2; Bb = B2; Y = Y2; N = N2; nt = ntile - (N1 >> 3); }
    const float* x0 = X + (size_t)(mtile * 4) * K;
    const float* w0 = W + (size_t)(nt * 8) * K;
    float acc[4][8];
#pragma unroll
    for (int i = 0; i < 4; i++)
#pragma unroll
        for (int j = 0; j < 8; j++) acc[i][j] = 0.f;
    for (int k = lane; k < K; k += 32) {
        float xv[4], wv[8];
#pragma unroll
        for (int i = 0; i < 4; i++) xv[i] = x0[(size_t)i * K + k];
#pragma unroll
        for (int j = 0; j < 8; j++) wv[j] = w0[(size_t)j * K + k];
#pragma unroll
        for (int i = 0; i < 4; i++)
#pragma unroll
            for (int j = 0; j < 8; j++) acc[i][j] = fmaf(xv[i], wv[j], acc[i][j]);
    }
#pragma unroll
    for (int o = 16; o; o >>= 1)
#pragma unroll
        for (int i = 0; i < 4; i++)
#pragma unroll
            for (int j = 0; j < 8; j++)
                acc[i][j] += __shfl_xor_sync(0xffffffffu, acc[i][j], o);
    int i = lane >> 3, j = lane & 7;
    float v = acc[i][j] + Bb[nt * 8 + j];
    if (doRelu) v = fmaxf(v, 0.f);
    Y[(size_t)(mtile * 4 + i) * N + nt * 8 + j] = v;
}

__global__ void warptile_kernel(const float* __restrict__ X, const float* __restrict__ W,
                                const float* __restrict__ bias, float* __restrict__ Y,
                                int M, int N, int K, int doRelu)
{
    int gw   = (blockIdx.x * blockDim.x + threadIdx.x) >> 5;
    int lane = threadIdx.x & 31;
    int nW = N >> 3;
    int mtile = gw / nW, ntile = gw - mtile * nW;
    if (mtile * 4 >= M) return;
    const float* x0 = X + (size_t)(mtile * 4) * K;
    const float* w0 = W + (size_t)(ntile * 8) * K;
    float acc[4][8];
#pragma unroll
    for (int i = 0; i < 4; i++)
#pragma unroll
        for (int j = 0; j < 8; j++) acc[i][j] = 0.f;
    for (int k = lane; k < K; k += 32) {
        float xv[4], wv[8];
#pragma unroll
        for (int i = 0; i < 4; i++) xv[i] = x0[(size_t)i * K + k];
#pragma unroll
        for (int j = 0; j < 8; j++) wv[j] = w0[(size_t)j * K + k];
#pragma unroll
        for (int i = 0; i < 4; i++)
#pragma unroll
            for (int j = 0; j < 8; j++) acc[i][j] = fmaf(xv[i], wv[j], acc[i][j]);
    }
#pragma unroll
    for (int o = 16; o; o >>= 1)
#pragma unroll
        for (int i = 0; i < 4; i++)
#pragma unroll
            for (int j = 0; j < 8; j++)
                acc[i][j] += __shfl_xor_sync(0xffffffffu, acc[i][j], o);
    int i = lane >> 3, j = lane & 7;
    float v = acc[i][j] + bias[ntile * 8 + j];
    if (doRelu) v = fmaxf(v, 0.f);
    Y[(size_t)(mtile * 4 + i) * N + ntile * 8 + j] = v;
}

// ---------------------------------------------------------------------------
// Attention + softmax -> fuse weights; final fuse.
// ---------------------------------------------------------------------------
__global__ void attn_kernel(const float* __restrict__ keys, const float* __restrict__ qq,
                            float* __restrict__ wf)
{
    int b = blockIdx.x;
    __shared__ float sA[5][5];
    int warp = threadIdx.x >> 5, lane = threadIdx.x & 31;
    for (int e = warp; e < 25; e += 8) {
        int i = e / 5, j = e - i * 5;
        const float4* kr = (const float4*)(keys + (size_t)(i * 32 + b) * 1024);
        const float4* qr = (const float4*)(qq + (size_t)(j * 32 + b) * 1024);
        float acc = 0.f;
        for (int k = lane; k < 256; k += 32) {
            float4 a = kr[k], c = qr[k];
            acc += a.x * c.x + a.y * c.y + a.z * c.z + a.w * c.w;
        }
#pragma unroll
        for (int o = 16; o; o >>= 1) acc += __shfl_xor_sync(0xffffffffu, acc, o);
        if (lane == 0) sA[i][j] = acc;
    }
    __syncthreads();
    if (threadIdx.x == 0) {
        float w[5] = {0.f, 0.f, 0.f, 0.f, 0.f};
        for (int j = 0; j < 5; j++) {
            float dd[4], mx = -1e30f;
            for (int r = 0; r < 4; r++) {
                dd[r] = (j > r) ? sA[r][j] : sA[r + 1][j];
                mx = fmaxf(mx, dd[r]);
            }
            float s = 0.f;
            for (int r = 0; r < 4; r++) { dd[r] = expf(dd[r] - mx); s += dd[r]; }
            float inv = 1.f / s;
            for (int r = 0; r < 4; r++) {
                int i = (j > r) ? r : r + 1;
                w[i] += dd[r] * inv;
            }
        }
        for (int i = 0; i < 5; i++) wf[b * 5 + i] = w[i] * 0.2f;
    }
}

__global__ void fuse_kernel(const float* __restrict__ bevs, const float* __restrict__ wf,
                            float* __restrict__ out)
{
    const int CHW = 256 * 16 * 16;
    int idx = blockIdx.x * blockDim.x + threadIdx.x;
    if (idx >= 32 * CHW) return;
    int b   = idx / CHW;
    int chw = idx - b * CHW;
    const float* base = bevs + ((size_t)b * 5) * CHW + chw;
    float acc = 0.f;
#pragma unroll
    for (int k = 0; k < 5; k++) acc += wf[b * 5 + k] * base[(size_t)k * CHW];
    out[idx] = acc;
}

// ---------------------------------------------------------------------------
extern "C" void kernel_launch(void* const* d_in, const int* in_sizes, int n_in,
                              void* d_out, int out_size)
{
    (void)in_sizes; (void)n_in; (void)out_size;
    const float* bevs = (const float*)d_in[0];
    const float *cw[5], *cs[5], *ct[5];
    for (int i = 0; i < 5; i++) {
        cw[i] = (const float*)d_in[1 + 3 * i];
        cs[i] = (const float*)d_in[2 + 3 * i];
        ct[i] = (const float*)d_in[3 + 3 * i];
    }
    const float* kw1 = (const float*)d_in[16]; const float* kb1 = (const float*)d_in[17];
    const float* kw2 = (const float*)d_in[18]; const float* kb2 = (const float*)d_in[19];
    const float* kw3 = (const float*)d_in[20]; const float* kb3 = (const float*)d_in[21];
    const float* qw1 = (const float*)d_in[22]; const float* qb1 = (const float*)d_in[23];
    const float* qw2 = (const float*)d_in[24]; const float* qb2 = (const float*)d_in[25];
    const float* qw3 = (const float*)d_in[26]; const float* qb3 = (const float*)d_in[27];
    const float* aw  = (const float*)d_in[28]; const float* ab  = (const float*)d_in[29];
    float* out = (float*)d_out;

    __nv_bfloat16 *a0h, *a0l, *b1h, *b1l, *b2h, *b2l, *b3h, *b3l, *b4h, *b4l;
    cudaGetSymbolAddress((void**)&a0h, g_a0h); cudaGetSymbolAddress((void**)&a0l, g_a0l);
    cudaGetSymbolAddress((void**)&b1h, g_b1h); cudaGetSymbolAddress((void**)&b1l, g_b1l);
    cudaGetSymbolAddress((void**)&b2h, g_b2h); cudaGetSymbolAddress((void**)&b2l, g_b2l);
    cudaGetSymbolAddress((void**)&b3h, g_b3h); cudaGetSymbolAddress((void**)&b3l, g_b3l);
    cudaGetSymbolAddress((void**)&b4h, g_b4h); cudaGetSymbolAddress((void**)&b4l, g_b4l);
    float *feat, *m1k, *m1q, *m2k, *m2q, *keys, *qrys, *qq, *wf;
    cudaGetSymbolAddress((void**)&feat, g_feat);
    cudaGetSymbolAddress((void**)&m1k, g_m1k);
    cudaGetSymbolAddress((void**)&m1q, g_m1q);
    cudaGetSymbolAddress((void**)&m2k, g_m2k);
    cudaGetSymbolAddress((void**)&m2q, g_m2q);
    cudaGetSymbolAddress((void**)&keys, g_keys);
    cudaGetSymbolAddress((void**)&qrys, g_qrys);
    cudaGetSymbolAddress((void**)&qq, g_qq);
    cudaGetSymbolAddress((void**)&wf, g_wf);
    __nv_bfloat16 *w1h, *w1l, *w2h, *w2l, *w3h, *w3l, *w4h, *w4l, *w5h, *w5l;
    cudaGetSymbolAddress((void**)&w1h, g_w1h); cudaGetSymbolAddress((void**)&w1l, g_w1l);
    cudaGetSymbolAddress((void**)&w2h, g_w2h); cudaGetSymbolAddress((void**)&w2l, g_w2l);
    cudaGetSymbolAddress((void**)&w3h, g_w3h); cudaGetSymbolAddress((void**)&w3l, g_w3l);
    cudaGetSymbolAddress((void**)&w4h, g_w4h); cudaGetSymbolAddress((void**)&w4l, g_w4l);
    cudaGetSymbolAddress((void**)&w5h, g_w5h); cudaGetSymbolAddress((void**)&w5l, g_w5l);

    constexpr int SMEM_L12 = 3 * 73728;   // 221184, 1 CTA/SM
    constexpr int SMEM_S   = 2 * 55296;   // 110592, 2 CTAs/SM

    cudaFuncSetAttribute(convMMA_kernel<256, 512, 16, 16, 1, 0, 128, 3, 1>,
                         cudaFuncAttributeMaxDynamicSharedMemorySize, SMEM_L12);
    cudaFuncSetAttribute(convMMA_kernel<512, 256, 16, 16, 1, 0, 128, 3, 1>,
                         cudaFuncAttributeMaxDynamicSharedMemorySize, SMEM_L12);
    cudaFuncSetAttribute(convMMA_kernel<256, 256, 16, 16, 2, 0, 64, 2, 2>,
                         cudaFuncAttributeMaxDynamicSharedMemorySize, SMEM_S);
    cudaFuncSetAttribute(convMMA_kernel<256, 256, 8, 8, 1, 0, 64, 2, 2>,
                         cudaFuncAttributeMaxDynamicSharedMemorySize, SMEM_S);
    cudaFuncSetAttribute(convMMA_kernel<256, 256, 8, 8, 2, 1, 64, 2, 2>,
                         cudaFuncAttributeMaxDynamicSharedMemorySize, SMEM_S);

    // ---- launch 0: all weight preps in one kernel ----
    {
        int t1 = 512 * 2304, t2 = 256 * 4608, t3 = 256 * 2304;
        WPrepDesc d0 = {cw[0], w1h, w1l, 256, t1, 0};
        WPrepDesc d1 = {cw[1], w2h, w2l, 512, t2, t1};
        WPrepDesc d2 = {cw[2], w3h, w3l, 256, t3, t1 + t2};
        WPrepDesc d3 = {cw[3], w4h, w4l, 256, t3, t1 + t2 + t3};
        WPrepDesc d4 = {cw[4], w5h, w5l, 256, t3, t1 + t2 + 2 * t3};
        int grand = t1 + t2 + 3 * t3;
        wprep_all_kernel<<<1184, 256>>>(d0, d1, d2, d3, d4, grand);
    }
    // ---- launch 1: bevs split ----
    actsplit_kernel<<<dim3(160, 8), 256>>>(bevs, a0h, a0l);

    // ---- launches 2..6: conv stack (conv2 at index 3 for ncu capture) ----
    convMMA_kernel<256, 512, 16, 16, 1, 0, 128, 3, 1><<<dim3(8, 160), 256, SMEM_L12>>>(
        a0h, a0l, w1h, w1l, cs[0], ct[0], b1h, b1l, nullptr);
    convMMA_kernel<512, 256, 16, 16, 1, 0, 128, 3, 1><<<dim3(4, 160), 256, SMEM_L12>>>(
        b1h, b1l, w2h, w2l, cs[1], ct[1], b2h, b2l, nullptr);
    convMMA_kernel<256, 256, 16, 16, 2, 0, 64, 2, 2><<<dim3(2, 160), 256, SMEM_S>>>(
        b2h, b2l, w3h, w3l, cs[2], ct[2], b3h, b3l, nullptr);
    convMMA_kernel<256, 256, 8, 8, 1, 0, 64, 2, 2><<<dim3(2, 160), 256, SMEM_S>>>(
        b3h, b3l, w4h, w4l, cs[3], ct[3], b4h, b4l, nullptr);
    convMMA_kernel<256, 256, 8, 8, 2, 1, 64, 2, 2><<<dim3(2, 40), 256, SMEM_S>>>(
        b4h, b4l, w5h, w5l, cs[4], ct[4], nullptr, nullptr, feat);

    // ---- fused k/q tail ----
    auto wt2 = [&](const float* X1, const float* W1, const float* B1, float* Y1, int N1,
                   const float* X2, const float* W2, const float* B2, float* Y2, int N2,
                   int M, int K, int relu) {
        int warps = (M / 4) * ((N1 + N2) / 8);
        warptile2_kernel<<<(warps + 7) / 8, 256>>>(X1, W1, B1, Y1, N1,
                                                   X2, W2, B2, Y2, N2, M, K, relu);
    };
    wt2(feat, kw1, kb1, m1k, 256, feat, qw1, qb1, m1q, 256, 160, 4096, 1);
    wt2(m1k, kw2, kb2, m2k, 128, m1q, qw2, qb2, m2q, 128, 160, 256, 1);
    wt2(m2k, kw3, kb3, keys, 1024, m2q, qw3, qb3, qrys, 32, 160, 128, 0);
    {
        int warps = (160 / 4) * (1024 / 8);
        warptile_kernel<<<(warps + 7) / 8, 256>>>(qrys, aw, ab, qq, 160, 1024, 32, 0);
    }

    attn_kernel<<<32, 256>>>(keys, qq, wf);
    fuse_kernel<<<(32 * 256 * 16 * 16 + 255) / 256, 256>>>(bevs, wf, out);
}

// round 9
// speedup vs baseline: 1.3206x; 1.0966x over previous
#include <cuda_runtime.h>
#include <cuda_bf16.h>
#include <cstdint>
#include <cstddef>

// ===========================================================================
// Who2com forward — split-bf16 mma.sync implicit-GEMM convs.
// R9: ALL convs MTILE=64 / 2-stage / 2 CTAs per SM (conv2 profile showed
// tensor=51%, occ=12.5% at 1 CTA/SM -> latency-bound; co-residency fix).
// ===========================================================================

__device__ __forceinline__ uint32_t smem_to_u32(const void* p) {
    uint32_t a;
    asm("{ .reg .u64 t; cvta.to.shared.u64 t, %1; cvt.u32.u64 %0, t; }"
        : "=r"(a) : "l"(p));
    return a;
}
__device__ __forceinline__ void ldsm_x4(uint32_t (&r)[4], uint32_t addr) {
    asm volatile("ldmatrix.sync.aligned.m8n8.x4.shared.b16 {%0,%1,%2,%3}, [%4];"
                 : "=r"(r[0]), "=r"(r[1]), "=r"(r[2]), "=r"(r[3]) : "r"(addr));
}
__device__ __forceinline__ void mma_bf16(float (&d)[4], const uint32_t (&a)[4],
                                         uint32_t b0, uint32_t b1) {
    asm volatile(
        "mma.sync.aligned.m16n8k16.row.col.f32.bf16.bf16.f32 "
        "{%0,%1,%2,%3}, {%4,%5,%6,%7}, {%8,%9}, {%0,%1,%2,%3};"
        : "+f"(d[0]), "+f"(d[1]), "+f"(d[2]), "+f"(d[3])
        : "r"(a[0]), "r"(a[1]), "r"(a[2]), "r"(a[3]), "r"(b0), "r"(b1));
}
__device__ __forceinline__ uint32_t pack_bf2(__nv_bfloat16 a, __nv_bfloat16 b) {
    __nv_bfloat162 t = __halves2bfloat162(a, b);
    return *reinterpret_cast<uint32_t*>(&t);
}
__device__ __forceinline__ void cp16(uint32_t dst, const void* src, bool v) {
    asm volatile("cp.async.cg.shared.global [%0], [%1], 16, %2;"
                 :: "r"(dst), "l"(src), "r"(v ? 16u : 0u) : "memory");
}
#define CP_COMMIT() asm volatile("cp.async.commit_group;" ::: "memory")

// ---------------------------------------------------------------------------
// Scratch
// ---------------------------------------------------------------------------
__device__ __align__(16) __nv_bfloat16 g_a0h[(size_t)160 * 256 * 256];
__device__ __align__(16) __nv_bfloat16 g_a0l[(size_t)160 * 256 * 256];
__device__ __align__(16) __nv_bfloat16 g_b1h[(size_t)160 * 256 * 512];
__device__ __align__(16) __nv_bfloat16 g_b1l[(size_t)160 * 256 * 512];
__device__ __align__(16) __nv_bfloat16 g_b2h[(size_t)160 * 256 * 256];
__device__ __align__(16) __nv_bfloat16 g_b2l[(size_t)160 * 256 * 256];
__device__ __align__(16) __nv_bfloat16 g_b3h[(size_t)160 * 64 * 256];
__device__ __align__(16) __nv_bfloat16 g_b3l[(size_t)160 * 64 * 256];
__device__ __align__(16) __nv_bfloat16 g_b4h[(size_t)160 * 64 * 256];
__device__ __align__(16) __nv_bfloat16 g_b4l[(size_t)160 * 64 * 256];
__device__ float g_feat[(size_t)160 * 4096];
__device__ float g_m1k[160 * 256], g_m1q[160 * 256];
__device__ float g_m2k[160 * 128], g_m2q[160 * 128];
__device__ float g_keys[160 * 1024];
__device__ float g_qrys[160 * 32];
__device__ float g_qq[160 * 1024];
__device__ float g_wf[32 * 5];
__device__ __align__(16) __nv_bfloat16 g_w1h[512 * 2304], g_w1l[512 * 2304];
__device__ __align__(16) __nv_bfloat16 g_w2h[256 * 4608], g_w2l[256 * 4608];
__device__ __align__(16) __nv_bfloat16 g_w3h[256 * 2304], g_w3l[256 * 2304];
__device__ __align__(16) __nv_bfloat16 g_w4h[256 * 2304], g_w4l[256 * 2304];
__device__ __align__(16) __nv_bfloat16 g_w5h[256 * 2304], g_w5l[256 * 2304];

// ---------------------------------------------------------------------------
// Merged weight prep: all 5 conv layers in one launch.
// ---------------------------------------------------------------------------
struct WPrepDesc {
    const float* src;
    __nv_bfloat16* hi;
    __nv_bfloat16* lo;
    int cin;
    int total;
    int base;
};

__global__ void wprep_all_kernel(WPrepDesc d0, WPrepDesc d1, WPrepDesc d2,
                                 WPrepDesc d3, WPrepDesc d4, int grand)
{
    WPrepDesc ds[5] = {d0, d1, d2, d3, d4};
    for (int g = blockIdx.x * blockDim.x + threadIdx.x; g < grand;
         g += gridDim.x * blockDim.x) {
        int li = 0;
#pragma unroll
        for (int t = 1; t < 5; t++)
            if (g >= ds[t].base) li = t;
        const WPrepDesc& d = ds[li];
        int idx = g - d.base;
        int cin9 = d.cin * 9;
        int co = idx / cin9;
        int rem = idx - co * cin9;
        int ci = rem / 9, tap = rem - ci * 9;
        float v = d.src[idx];
        __nv_bfloat16 h = __float2bfloat16(v);
        __nv_bfloat16 l = __float2bfloat16(v - __bfloat162float(h));
        size_t dd = (size_t)co * cin9 + tap * d.cin + ci;
        d.hi[dd] = h; d.lo[dd] = l;
    }
}

// bevs NCHW fp32 -> NHWC hi/lo bf16.
__global__ void actsplit_kernel(const float* __restrict__ in,
                                __nv_bfloat16* __restrict__ oh,
                                __nv_bfloat16* __restrict__ ol)
{
    __shared__ float s[32][257];
    int n = blockIdx.x, c0 = blockIdx.y * 32;
    int tid = threadIdx.x;
#pragma unroll
    for (int it = 0; it < 32; it++)
        s[it][tid] = in[((size_t)n * 256 + c0 + it) * 256 + tid];
    __syncthreads();
    int ci = tid & 31, p0 = tid >> 5;
#pragma unroll
    for (int pp = 0; pp < 32; pp++) {
        int pix = p0 + pp * 8;
        float v = s[ci][pix];
        __nv_bfloat16 h = __float2bfloat16(v);
        __nv_bfloat16 l = __float2bfloat16(v - __bfloat162float(h));
        size_t o = ((size_t)n * 256 + pix) * 256 + c0 + ci;
        oh[o] = h; ol[o] = l;
    }
}

// ---------------------------------------------------------------------------
// Implicit-GEMM conv3x3 (pad=1) + affine + ReLU, split-bf16 mma.sync.
// K-chunks of 64 (144B pitch), circular STAGES cp.async pipeline, one
// __syncthreads per chunk.
// ---------------------------------------------------------------------------
static constexpr int SPB = 144;

template <int CIN, int COUT, int HIN, int WIN, int STRIDE, int OUTMODE,
          int MTILE, int STAGES, int MINCTA>
__global__ void __launch_bounds__(256, MINCTA)
convMMA_kernel(const __nv_bfloat16* __restrict__ aH, const __nv_bfloat16* __restrict__ aL,
               const __nv_bfloat16* __restrict__ wH, const __nv_bfloat16* __restrict__ wL,
               const float* __restrict__ scale, const float* __restrict__ shift,
               __nv_bfloat16* __restrict__ oH, __nv_bfloat16* __restrict__ oL,
               float* __restrict__ oF)
{
    constexpr int HO   = (HIN - 1) / STRIDE + 1;
    constexpr int WO   = (WIN - 1) / STRIDE + 1;
    constexpr int MPIX = HO * WO;
    constexpr int NIMG = (MPIX >= MTILE) ? 1 : (MTILE / MPIX);
    constexpr int NT   = COUT / 128;
    constexpr int KTOT = 9 * CIN;
    constexpr int CPT  = CIN / 64;
    constexpr int NCH  = 9 * CPT;
    constexpr int MW   = MTILE / 32;
    constexpr int NW   = 8 / MW;
    constexpr int NCPW = 128 / NW;
    constexpr int NT2  = NCPW / 16;
    constexpr int STB  = (MTILE + 128) * 2 * SPB;
    constexpr int A_LO = MTILE * SPB;
    constexpr int B_HI = MTILE * 2 * SPB;
    constexpr int B_LO = B_HI + 128 * SPB;
    constexpr int RT   = (MTILE + 128) * 16;

    extern __shared__ char smem[];
    const uint32_t sb = smem_to_u32(smem);

    const int tid = threadIdx.x, wid = tid >> 5, lane = tid & 31;
    const int mt  = blockIdx.x / NT;
    const int co0 = (blockIdx.x % NT) * 128;
    const int n0  = blockIdx.y * NIMG;
    const int wm  = wid % MW;
    const int wn  = wid / MW;

    auto issue = [&](int c) {
        const uint32_t st = sb + (uint32_t)(c % STAGES) * STB;
        const int tap = c / CPT;
        const int ci0 = (c - tap * CPT) * 64;
        const int dy = tap / 3 - 1, dx = tap % 3 - 1;
#pragma unroll
        for (int i = tid; i < RT; i += 256) {
            const int row  = i >> 4;
            const int seg  = i & 7;
            const int half = (i >> 3) & 1;
            if (row < MTILE) {
                int g = mt * MTILE + row;
                int img = g / MPIX, pix = g % MPIX;
                int oh = pix / WO, ow = pix - oh * WO;
                int ih = oh * STRIDE + dy, iw = ow * STRIDE + dx;
                bool v = ((unsigned)ih < (unsigned)HIN) && ((unsigned)iw < (unsigned)WIN);
                int ihs = v ? ih : 0, iws = v ? iw : 0;
                size_t aoff = (((size_t)(n0 + img) * HIN + ihs) * WIN + iws) * CIN
                              + ci0 + seg * 8;
                uint32_t ad = st + (uint32_t)half * A_LO + (uint32_t)row * SPB + seg * 16;
                cp16(ad, (half ? aL : aH) + aoff, v);
            } else {
                int r2 = row - MTILE;
                size_t woff = (size_t)(co0 + r2) * KTOT + (size_t)c * 64 + seg * 8;
                uint32_t bd = st + B_HI + (uint32_t)half * (128 * SPB)
                              + (uint32_t)r2 * SPB + seg * 16;
                cp16(bd, (half ? wL : wH) + woff, true);
            }
        }
        CP_COMMIT();
    };

    float acc[2][NT2 * 2][4];
#pragma unroll
    for (int a = 0; a < 2; a++)
#pragma unroll
        for (int b = 0; b < NT2 * 2; b++)
#pragma unroll
            for (int c = 0; c < 4; c++) acc[a][b][c] = 0.f;

#pragma unroll
    for (int p = 0; p < STAGES - 1; p++) issue(p);

    for (int c = 0; c < NCH; c++) {
        asm volatile("cp.async.wait_group %0;" :: "n"(STAGES - 2) : "memory");
        __syncthreads();
        if (c + STAGES - 1 < NCH) issue(c + STAGES - 1);
        else CP_COMMIT();

        const uint32_t st  = sb + (uint32_t)(c % STAGES) * STB;
        const uint32_t sAh = st, sAl = st + A_LO, sBh = st + B_HI, sBl = st + B_LO;
#pragma unroll
        for (int ks = 0; ks < 4; ks++) {
            const uint32_t acol = (uint32_t)ks * 32u + ((lane >> 4) << 4);
            uint32_t ah[2][4], al2[2][4];
#pragma unroll
            for (int m2 = 0; m2 < 2; m2++) {
                uint32_t arow = (uint32_t)(wm * 32 + m2 * 16 + (lane & 15));
                ldsm_x4(ah[m2],  sAh + arow * SPB + acol);
                ldsm_x4(al2[m2], sAl + arow * SPB + acol);
            }
#pragma unroll
            for (int nt2 = 0; nt2 < NT2; nt2++) {
                uint32_t brow = (uint32_t)(wn * NCPW + nt2 * 16 +
                                           ((lane >> 4) << 3) + (lane & 7));
                uint32_t bcol = (uint32_t)ks * 32u + (((lane >> 3) & 1) << 4);
                uint32_t bh[4], bl4[4];
                ldsm_x4(bh, sBh + brow * SPB + bcol);
#pragma unroll
                for (int m2 = 0; m2 < 2; m2++) {
                    mma_bf16(acc[m2][nt2 * 2],     ah[m2], bh[0], bh[1]);
                    mma_bf16(acc[m2][nt2 * 2 + 1], ah[m2], bh[2], bh[3]);
                }
                ldsm_x4(bl4, sBl + brow * SPB + bcol);
#pragma unroll
                for (int m2 = 0; m2 < 2; m2++) {
                    mma_bf16(acc[m2][nt2 * 2],     ah[m2], bl4[0], bl4[1]);
                    mma_bf16(acc[m2][nt2 * 2 + 1], ah[m2], bl4[2], bl4[3]);
                    mma_bf16(acc[m2][nt2 * 2],     al2[m2], bh[0], bh[1]);
                    mma_bf16(acc[m2][nt2 * 2 + 1], al2[m2], bh[2], bh[3]);
                }
            }
        }
    }

    if (OUTMODE == 0) {
#pragma unroll
        for (int m2 = 0; m2 < 2; m2++) {
            int mA = wm * 32 + m2 * 16 + (lane >> 2);
            int gA = mt * MTILE + mA;
            int gB = gA + 8;
            size_t rowA = ((size_t)(n0 + gA / MPIX) * MPIX + gA % MPIX) * COUT;
            size_t rowB = ((size_t)(n0 + gB / MPIX) * MPIX + gB % MPIX) * COUT;
#pragma unroll
            for (int j = 0; j < NT2 * 2; j++) {
                int co = co0 + wn * NCPW + j * 8 + (lane & 3) * 2;
                float s0 = __ldg(scale + co), s1 = __ldg(scale + co + 1);
                float t0 = __ldg(shift + co), t1 = __ldg(shift + co + 1);
                float v0 = fmaxf(fmaf(acc[m2][j][0], s0, t0), 0.f);
                float v1 = fmaxf(fmaf(acc[m2][j][1], s1, t1), 0.f);
                float v2 = fmaxf(fmaf(acc[m2][j][2], s0, t0), 0.f);
                float v3 = fmaxf(fmaf(acc[m2][j][3], s1, t1), 0.f);
                __nv_bfloat16 h0 = __float2bfloat16(v0), h1 = __float2bfloat16(v1);
                __nv_bfloat16 h2 = __float2bfloat16(v2), h3 = __float2bfloat16(v3);
                __nv_bfloat16 l0 = __float2bfloat16(v0 - __bfloat162float(h0));
                __nv_bfloat16 l1 = __float2bfloat16(v1 - __bfloat162float(h1));
                __nv_bfloat16 l2 = __float2bfloat16(v2 - __bfloat162float(h2));
                __nv_bfloat16 l3 = __float2bfloat16(v3 - __bfloat162float(h3));
                *reinterpret_cast<uint32_t*>(oH + rowA + co) = pack_bf2(h0, h1);
                *reinterpret_cast<uint32_t*>(oL + rowA + co) = pack_bf2(l0, l1);
                *reinterpret_cast<uint32_t*>(oH + rowB + co) = pack_bf2(h2, h3);
                *reinterpret_cast<uint32_t*>(oL + rowB + co) = pack_bf2(l2, l3);
            }
        }
    } else {
        constexpr int OPITCH = MTILE + 4;
        float* sOut = reinterpret_cast<float*>(smem);
        __syncthreads();
#pragma unroll
        for (int m2 = 0; m2 < 2; m2++) {
#pragma unroll
            for (int j = 0; j < NT2 * 2; j++) {
                int m = wm * 32 + m2 * 16 + (lane >> 2);
                int nn = wn * NCPW + j * 8 + (lane & 3) * 2;
                sOut[(size_t)nn * OPITCH + m]           = acc[m2][j][0];
                sOut[(size_t)(nn + 1) * OPITCH + m]     = acc[m2][j][1];
                sOut[(size_t)nn * OPITCH + m + 8]       = acc[m2][j][2];
                sOut[(size_t)(nn + 1) * OPITCH + m + 8] = acc[m2][j][3];
            }
        }
        __syncthreads();
        int row = tid >> 1, half = tid & 1;
        int co = co0 + row;
        float s = __ldg(scale + co), t = __ldg(shift + co);
#pragma unroll
        for (int q = 0; q < MTILE / 8; q++) {
            int m = half * (MTILE / 2) + q * 4;
            float4 v = *reinterpret_cast<float4*>(&sOut[(size_t)row * OPITCH + m]);
            v.x = fmaxf(fmaf(v.x, s, t), 0.f);
            v.y = fmaxf(fmaf(v.y, s, t), 0.f);
            v.z = fmaxf(fmaf(v.z, s, t), 0.f);
            v.w = fmaxf(fmaf(v.w, s, t), 0.f);
            int g = mt * MTILE + m;
            int img = g / MPIX, pix = g % MPIX;
            *reinterpret_cast<float4*>(
                &oF[((size_t)(n0 + img) * COUT + co) * MPIX + pix]) = v;
        }
    }
}

// ---------------------------------------------------------------------------
// Warp-tile GEMV over TWO independent (X,W,b,Y,N) sets in one launch.
// ---------------------------------------------------------------------------
__global__ void warptile2_kernel(const float* __restrict__ X1, const float* __restrict__ W1,
                                 const float* __restrict__ B1, float* __restrict__ Y1, int N1,
                                 const float* __restrict__ X2, const float* __restrict__ W2,
                                 const float* __restrict__ B2, float* __restrict__ Y2, int N2,
                                 int M, int K, int doRelu)
{
    int gw   = (blockIdx.x * blockDim.x + threadIdx.x) >> 5;
    int lane = threadIdx.x & 31;
    int nWtot = (N1 + N2) >> 3;
    int mtile = gw / nWtot, ntile = gw - mtile * nWtot;
    if (mtile * 4 >= M) return;
    const float *X, *W, *Bb;
    float* Y;
    int N, nt;
    if (ntile < (N1 >> 3)) { X = X1; W = W1; Bb = B1; Y = Y1; N = N1; nt = ntile; }
    else { X = X2; W = W2; Bb = B2; Y = Y2; N = N2; nt = ntile - (N1 >> 3); }
    const float* x0 = X + (size_t)(mtile * 4) * K;
    const float* w0 = W + (size_t)(nt * 8) * K;
    float acc[4][8];
#pragma unroll
    for (int i = 0; i < 4; i++)
#pragma unroll
        for (int j = 0; j < 8; j++) acc[i][j] = 0.f;
    for (int k = lane; k < K; k += 32) {
        float xv[4], wv[8];
#pragma unroll
        for (int i = 0; i < 4; i++) xv[i] = x0[(size_t)i * K + k];
#pragma unroll
        for (int j = 0; j < 8; j++) wv[j] = w0[(size_t)j * K + k];
#pragma unroll
        for (int i = 0; i < 4; i++)
#pragma unroll
            for (int j = 0; j < 8; j++) acc[i][j] = fmaf(xv[i], wv[j], acc[i][j]);
    }
#pragma unroll
    for (int o = 16; o; o >>= 1)
#pragma unroll
        for (int i = 0; i < 4; i++)
#pragma unroll
            for (int j = 0; j < 8; j++)
                acc[i][j] += __shfl_xor_sync(0xffffffffu, acc[i][j], o);
    int i = lane >> 3, j = lane & 7;
    float v = acc[i][j] + Bb[nt * 8 + j];
    if (doRelu) v = fmaxf(v, 0.f);
    Y[(size_t)(mtile * 4 + i) * N + nt * 8 + j] = v;
}

__global__ void warptile_kernel(const float* __restrict__ X, const float* __restrict__ W,
                                const float* __restrict__ bias, float* __restrict__ Y,
                                int M, int N, int K, int doRelu)
{
    int gw   = (blockIdx.x * blockDim.x + threadIdx.x) >> 5;
    int lane = threadIdx.x & 31;
    int nW = N >> 3;
    int mtile = gw / nW, ntile = gw - mtile * nW;
    if (mtile * 4 >= M) return;
    const float* x0 = X + (size_t)(mtile * 4) * K;
    const float* w0 = W + (size_t)(ntile * 8) * K;
    float acc[4][8];
#pragma unroll
    for (int i = 0; i < 4; i++)
#pragma unroll
        for (int j = 0; j < 8; j++) acc[i][j] = 0.f;
    for (int k = lane; k < K; k += 32) {
        float xv[4], wv[8];
#pragma unroll
        for (int i = 0; i < 4; i++) xv[i] = x0[(size_t)i * K + k];
#pragma unroll
        for (int j = 0; j < 8; j++) wv[j] = w0[(size_t)j * K + k];
#pragma unroll
        for (int i = 0; i < 4; i++)
#pragma unroll
            for (int j = 0; j < 8; j++) acc[i][j] = fmaf(xv[i], wv[j], acc[i][j]);
    }
#pragma unroll
    for (int o = 16; o; o >>= 1)
#pragma unroll
        for (int i = 0; i < 4; i++)
#pragma unroll
            for (int j = 0; j < 8; j++)
                acc[i][j] += __shfl_xor_sync(0xffffffffu, acc[i][j], o);
    int i = lane >> 3, j = lane & 7;
    float v = acc[i][j] + bias[ntile * 8 + j];
    if (doRelu) v = fmaxf(v, 0.f);
    Y[(size_t)(mtile * 4 + i) * N + ntile * 8 + j] = v;
}

// ---------------------------------------------------------------------------
// Attention + softmax -> fuse weights; final fuse.
// ---------------------------------------------------------------------------
__global__ void attn_kernel(const float* __restrict__ keys, const float* __restrict__ qq,
                            float* __restrict__ wf)
{
    int b = blockIdx.x;
    __shared__ float sA[5][5];
    int warp = threadIdx.x >> 5, lane = threadIdx.x & 31;
    for (int e = warp; e < 25; e += 8) {
        int i = e / 5, j = e - i * 5;
        const float4* kr = (const float4*)(keys + (size_t)(i * 32 + b) * 1024);
        const float4* qr = (const float4*)(qq + (size_t)(j * 32 + b) * 1024);
        float acc = 0.f;
        for (int k = lane; k < 256; k += 32) {
            float4 a = kr[k], c = qr[k];
            acc += a.x * c.x + a.y * c.y + a.z * c.z + a.w * c.w;
        }
#pragma unroll
        for (int o = 16; o; o >>= 1) acc += __shfl_xor_sync(0xffffffffu, acc, o);
        if (lane == 0) sA[i][j] = acc;
    }
    __syncthreads();
    if (threadIdx.x == 0) {
        float w[5] = {0.f, 0.f, 0.f, 0.f, 0.f};
        for (int j = 0; j < 5; j++) {
            float dd[4], mx = -1e30f;
            for (int r = 0; r < 4; r++) {
                dd[r] = (j > r) ? sA[r][j] : sA[r + 1][j];
                mx = fmaxf(mx, dd[r]);
            }
            float s = 0.f;
            for (int r = 0; r < 4; r++) { dd[r] = expf(dd[r] - mx); s += dd[r]; }
            float inv = 1.f / s;
            for (int r = 0; r < 4; r++) {
                int i = (j > r) ? r : r + 1;
                w[i] += dd[r] * inv;
            }
        }
        for (int i = 0; i < 5; i++) wf[b * 5 + i] = w[i] * 0.2f;
    }
}

__global__ void fuse_kernel(const float* __restrict__ bevs, const float* __restrict__ wf,
                            float* __restrict__ out)
{
    const int CHW = 256 * 16 * 16;
    int idx = blockIdx.x * blockDim.x + threadIdx.x;
    if (idx >= 32 * CHW) return;
    int b   = idx / CHW;
    int chw = idx - b * CHW;
    const float* base = bevs + ((size_t)b * 5) * CHW + chw;
    float acc = 0.f;
#pragma unroll
    for (int k = 0; k < 5; k++) acc += wf[b * 5 + k] * base[(size_t)k * CHW];
    out[idx] = acc;
}

// ---------------------------------------------------------------------------
extern "C" void kernel_launch(void* const* d_in, const int* in_sizes, int n_in,
                              void* d_out, int out_size)
{
    (void)in_sizes; (void)n_in; (void)out_size;
    const float* bevs = (const float*)d_in[0];
    const float *cw[5], *cs[5], *ct[5];
    for (int i = 0; i < 5; i++) {
        cw[i] = (const float*)d_in[1 + 3 * i];
        cs[i] = (const float*)d_in[2 + 3 * i];
        ct[i] = (const float*)d_in[3 + 3 * i];
    }
    const float* kw1 = (const float*)d_in[16]; const float* kb1 = (const float*)d_in[17];
    const float* kw2 = (const float*)d_in[18]; const float* kb2 = (const float*)d_in[19];
    const float* kw3 = (const float*)d_in[20]; const float* kb3 = (const float*)d_in[21];
    const float* qw1 = (const float*)d_in[22]; const float* qb1 = (const float*)d_in[23];
    const float* qw2 = (const float*)d_in[24]; const float* qb2 = (const float*)d_in[25];
    const float* qw3 = (const float*)d_in[26]; const float* qb3 = (const float*)d_in[27];
    const float* aw  = (const float*)d_in[28]; const float* ab  = (const float*)d_in[29];
    float* out = (float*)d_out;

    __nv_bfloat16 *a0h, *a0l, *b1h, *b1l, *b2h, *b2l, *b3h, *b3l, *b4h, *b4l;
    cudaGetSymbolAddress((void**)&a0h, g_a0h); cudaGetSymbolAddress((void**)&a0l, g_a0l);
    cudaGetSymbolAddress((void**)&b1h, g_b1h); cudaGetSymbolAddress((void**)&b1l, g_b1l);
    cudaGetSymbolAddress((void**)&b2h, g_b2h); cudaGetSymbolAddress((void**)&b2l, g_b2l);
    cudaGetSymbolAddress((void**)&b3h, g_b3h); cudaGetSymbolAddress((void**)&b3l, g_b3l);
    cudaGetSymbolAddress((void**)&b4h, g_b4h); cudaGetSymbolAddress((void**)&b4l, g_b4l);
    float *feat, *m1k, *m1q, *m2k, *m2q, *keys, *qrys, *qq, *wf;
    cudaGetSymbolAddress((void**)&feat, g_feat);
    cudaGetSymbolAddress((void**)&m1k, g_m1k);
    cudaGetSymbolAddress((void**)&m1q, g_m1q);
    cudaGetSymbolAddress((void**)&m2k, g_m2k);
    cudaGetSymbolAddress((void**)&m2q, g_m2q);
    cudaGetSymbolAddress((void**)&keys, g_keys);
    cudaGetSymbolAddress((void**)&qrys, g_qrys);
    cudaGetSymbolAddress((void**)&qq, g_qq);
    cudaGetSymbolAddress((void**)&wf, g_wf);
    __nv_bfloat16 *w1h, *w1l, *w2h, *w2l, *w3h, *w3l, *w4h, *w4l, *w5h, *w5l;
    cudaGetSymbolAddress((void**)&w1h, g_w1h); cudaGetSymbolAddress((void**)&w1l, g_w1l);
    cudaGetSymbolAddress((void**)&w2h, g_w2h); cudaGetSymbolAddress((void**)&w2l, g_w2l);
    cudaGetSymbolAddress((void**)&w3h, g_w3h); cudaGetSymbolAddress((void**)&w3l, g_w3l);
    cudaGetSymbolAddress((void**)&w4h, g_w4h); cudaGetSymbolAddress((void**)&w4l, g_w4l);
    cudaGetSymbolAddress((void**)&w5h, g_w5h); cudaGetSymbolAddress((void**)&w5l, g_w5l);

    // MTILE=64, 2-stage: 110592 B -> 2 CTAs/SM everywhere
    constexpr int SMEM_S = 2 * 55296;

    cudaFuncSetAttribute(convMMA_kernel<256, 512, 16, 16, 1, 0, 64, 2, 2>,
                         cudaFuncAttributeMaxDynamicSharedMemorySize, SMEM_S);
    cudaFuncSetAttribute(convMMA_kernel<512, 256, 16, 16, 1, 0, 64, 2, 2>,
                         cudaFuncAttributeMaxDynamicSharedMemorySize, SMEM_S);
    cudaFuncSetAttribute(convMMA_kernel<256, 256, 16, 16, 2, 0, 64, 2, 2>,
                         cudaFuncAttributeMaxDynamicSharedMemorySize, SMEM_S);
    cudaFuncSetAttribute(convMMA_kernel<256, 256, 8, 8, 1, 0, 64, 2, 2>,
                         cudaFuncAttributeMaxDynamicSharedMemorySize, SMEM_S);
    cudaFuncSetAttribute(convMMA_kernel<256, 256, 8, 8, 2, 1, 64, 2, 2>,
                         cudaFuncAttributeMaxDynamicSharedMemorySize, SMEM_S);

    // ---- launch 0: all weight preps in one kernel ----
    {
        int t1 = 512 * 2304, t2 = 256 * 4608, t3 = 256 * 2304;
        WPrepDesc d0 = {cw[0], w1h, w1l, 256, t1, 0};
        WPrepDesc d1 = {cw[1], w2h, w2l, 512, t2, t1};
        WPrepDesc d2 = {cw[2], w3h, w3l, 256, t3, t1 + t2};
        WPrepDesc d3 = {cw[3], w4h, w4l, 256, t3, t1 + t2 + t3};
        WPrepDesc d4 = {cw[4], w5h, w5l, 256, t3, t1 + t2 + 2 * t3};
        int grand = t1 + t2 + 3 * t3;
        wprep_all_kernel<<<1184, 256>>>(d0, d1, d2, d3, d4, grand);
    }
    // ---- launch 1: bevs split ----
    actsplit_kernel<<<dim3(160, 8), 256>>>(bevs, a0h, a0l);

    // ---- launches 2..6: conv stack, all MTILE=64 @ 2 CTAs/SM ----
    convMMA_kernel<256, 512, 16, 16, 1, 0, 64, 2, 2><<<dim3(16, 160), 256, SMEM_S>>>(
        a0h, a0l, w1h, w1l, cs[0], ct[0], b1h, b1l, nullptr);
    convMMA_kernel<512, 256, 16, 16, 1, 0, 64, 2, 2><<<dim3(8, 160), 256, SMEM_S>>>(
        b1h, b1l, w2h, w2l, cs[1], ct[1], b2h, b2l, nullptr);
    convMMA_kernel<256, 256, 16, 16, 2, 0, 64, 2, 2><<<dim3(2, 160), 256, SMEM_S>>>(
        b2h, b2l, w3h, w3l, cs[2], ct[2], b3h, b3l, nullptr);
    convMMA_kernel<256, 256, 8, 8, 1, 0, 64, 2, 2><<<dim3(2, 160), 256, SMEM_S>>>(
        b3h, b3l, w4h, w4l, cs[3], ct[3], b4h, b4l, nullptr);
    convMMA_kernel<256, 256, 8, 8, 2, 1, 64, 2, 2><<<dim3(2, 40), 256, SMEM_S>>>(
        b4h, b4l, w5h, w5l, cs[4], ct[4], nullptr, nullptr, feat);

    // ---- fused k/q tail ----
    auto wt2 = [&](const float* X1, const float* W1, const float* B1, float* Y1, int N1,
                   const float* X2, const float* W2, const float* B2, float* Y2, int N2,
                   int M, int K, int relu) {
        int warps = (M / 4) * ((N1 + N2) / 8);
        warptile2_kernel<<<(warps + 7) / 8, 256>>>(X1, W1, B1, Y1, N1,
                                                   X2, W2, B2, Y2, N2, M, K, relu);
    };
    wt2(feat, kw1, kb1, m1k, 256, feat, qw1, qb1, m1q, 256, 160, 4096, 1);
    wt2(m1k, kw2, kb2, m2k, 128, m1q, qw2, qb2, m2q, 128, 160, 256, 1);
    wt2(m2k, kw3, kb3, keys, 1024, m2q, qw3, qb3, qrys, 32, 160, 128, 0);
    {
        int warps = (160 / 4) * (1024 / 8);
        warptile_kernel<<<(warps + 7) / 8, 256>>>(qrys, aw, ab, qq, 160, 1024, 32, 0);
    }

    attn_kernel<<<32, 256>>>(keys, qq, wf);
    fuse_kernel<<<(32 * 256 * 16 * 16 + 255) / 256, 256>>>(bevs, wf, out);
}